// round 1
// baseline (speedup 1.0000x reference)
#include <cuda_runtime.h>
#include <math.h>

#define B  4
#define C  64
#define CR 32
#define HH 256
#define WWI 256
#define HW 65536

// ---------------- scratch (device globals; no allocation allowed) ----------
__device__ float d_avg[2][B][C];
__device__ float d_mx [2][B][C];
__device__ float d_S  [2][B][C*C];      // S1, S2 (row-softmaxed)
__device__ float d_wv [2][B][C];        // column means of S (for mean-pool)
__device__ float d_pooled[2][B][2][HW]; // [z][b][{mean,max}][pix]
__device__ float d_t1[2][B][HW];        // conv1 output (relu'd)
__device__ float d_t2[2][B][HW];        // conv2 output (pre-softmax logits)
__device__ float d_smax[2][B];
__device__ float d_ssum[2][B];

// packed f32x2 FMA (Blackwell): 2x fp32 FMA throughput vs scalar FFMA
__device__ __forceinline__ float2 ffma2(float2 a, float2 b, float2 c) {
    unsigned long long ra = *reinterpret_cast<unsigned long long*>(&a);
    unsigned long long rb = *reinterpret_cast<unsigned long long*>(&b);
    unsigned long long rc = *reinterpret_cast<unsigned long long*>(&c);
    unsigned long long rd;
    asm("fma.rn.f32x2 %0, %1, %2, %3;" : "=l"(rd) : "l"(ra), "l"(rb), "l"(rc));
    return *reinterpret_cast<float2*>(&rd);
}

// ---------------- kernel 1: per-(input,b,c) mean & max over HW -------------
__global__ void stats_kernel(const float* __restrict__ f1,
                             const float* __restrict__ f2) {
    int row = blockIdx.x;            // 0..511
    int z   = row >> 8;
    int idx = row & 255;             // b*64 + c
    const float* f = (z ? f2 : f1) + (size_t)idx * HW;
    int tid = threadIdx.x;

    float s = 0.f, m = -INFINITY;
    const float4* f4 = (const float4*)f;
    for (int i = tid; i < HW / 4; i += 256) {
        float4 v = f4[i];
        s += (v.x + v.y) + (v.z + v.w);
        m = fmaxf(m, fmaxf(fmaxf(v.x, v.y), fmaxf(v.z, v.w)));
    }
    __shared__ float ss[256], sm[256];
    ss[tid] = s; sm[tid] = m;
    __syncthreads();
    for (int o = 128; o > 0; o >>= 1) {
        if (tid < o) { ss[tid] += ss[tid + o]; sm[tid] = fmaxf(sm[tid], sm[tid + o]); }
        __syncthreads();
    }
    if (tid == 0) {
        d_avg[z][idx >> 6][idx & 63] = ss[0] * (1.f / HW);
        d_mx [z][idx >> 6][idx & 63] = sm[0];
    }
}

// ---------------- kernel 2: MLPs + rank-1 cross softmax --------------------
__global__ void mlp_kernel(
    const float* __restrict__ w_a1,  const float* __restrict__ b_a1,
    const float* __restrict__ w_m1,  const float* __restrict__ b_m1,
    const float* __restrict__ w_a11, const float* __restrict__ b_a11,
    const float* __restrict__ w_m11, const float* __restrict__ b_m11,
    const float* __restrict__ w_a2,  const float* __restrict__ b_a2,
    const float* __restrict__ w_m2,  const float* __restrict__ b_m2,
    const float* __restrict__ w_a22, const float* __restrict__ b_a22,
    const float* __restrict__ w_m22, const float* __restrict__ b_m22)
{
    __shared__ float s_stat[4][B][C];  // avg1,max1,avg2,max2
    __shared__ float s_hid [4][B][CR];
    __shared__ float s_a   [2][B][C];
    int tid = threadIdx.x;

    { // phase 0: stage stats (256 entries per array)
        int b = tid >> 6, c = tid & 63;
        s_stat[0][b][c] = d_avg[0][b][c];
        s_stat[1][b][c] = d_mx [0][b][c];
        s_stat[2][b][c] = d_avg[1][b][c];
        s_stat[3][b][c] = d_mx [1][b][c];
    }
    __syncthreads();

    // phase 1: hidden = relu(stat @ W^T + bias), 4 paths x B x CR = 512
    const float* Wp[4] = {w_a1, w_m1, w_a2, w_m2};
    const float* Bp[4] = {b_a1, b_m1, b_a2, b_m2};
    for (int e = tid; e < 4 * B * CR; e += 256) {
        int p = e >> 7, b = (e >> 5) & 3, k = e & 31;
        const float* wr = Wp[p] + k * C;
        float acc = Bp[p][k];
        #pragma unroll 8
        for (int c2 = 0; c2 < C; c2++) acc += s_stat[p][b][c2] * wr[c2];
        s_hid[p][b][k] = fmaxf(acc, 0.f);
    }
    __syncthreads();

    { // phase 2: a = hid_avg @ Waa^T + baa + hid_max @ Wmm^T + bmm
        int b = tid >> 6, i = tid & 63;
        float a1 = b_a11[i] + b_m11[i];
        float a2 = b_a22[i] + b_m22[i];
        #pragma unroll 8
        for (int k = 0; k < CR; k++) {
            a1 += s_hid[0][b][k] * w_a11[i * CR + k] + s_hid[1][b][k] * w_m11[i * CR + k];
            a2 += s_hid[2][b][k] * w_a22[i * CR + k] + s_hid[3][b][k] * w_m22[i * CR + k];
        }
        s_a[0][b][i] = a1;
        s_a[1][b][i] = a2;
    }
    __syncthreads();

    { // phase 3: S[zz][b] rows = softmax_j(a_zz[i] * a_other[j])
        int b = tid >> 6, i = tid & 63;
        for (int zz = 0; zz < 2; zz++) {
            float x = s_a[zz][b][i];
            const float* other = s_a[1 - zz][b];
            float m = -INFINITY;
            for (int j = 0; j < C; j++) m = fmaxf(m, x * other[j]);
            float* Srow = &d_S[zz][b][i * C];
            float Z = 0.f;
            for (int j = 0; j < C; j++) {
                float e2 = __expf(x * other[j] - m);
                Srow[j] = e2;
                Z += e2;
            }
            float inv = 1.f / Z;
            for (int j = 0; j < C; j++) Srow[j] *= inv;
        }
    }
    __syncthreads();

    { // phase 4: w[zz][b][j] = mean_i S[zz][b][i][j]
        int b = tid >> 6, j = tid & 63;
        for (int zz = 0; zz < 2; zz++) {
            float s = 0.f;
            for (int i2 = 0; i2 < C; i2++) s += d_S[zz][b][i2 * C + j];
            d_wv[zz][b][j] = s * (1.f / C);
        }
    }
}

// ---------------- kernel 3: attention pooling (mean & max over channels) ---
// Per (z,b,pixel-tile): at[i,p] = sum_j S[i,j]*f[j,p]; emit mean_i, max_i.
// 256 threads: 64 pixel-groups (4 px each as 2x f32x2) x 4 i-groups (16 i).
#define ATP_SMEM_FLOATS (8192 + 16384 + 64 + 1024)
__global__ void __launch_bounds__(256, 2)
atpool_kernel(const float* __restrict__ f1, const float* __restrict__ f2) {
    extern __shared__ float smem[];
    float2* sS  = (float2*)smem;          // 4096 float2 (S duplicated), 32KB
    float*  sF  = smem + 8192;            // 64 x 256 tile, 64KB
    float*  sw  = sF + 64 * 256;          // 64
    float*  red = sw + 64;                // 4 x 64 x 4

    int tid  = threadIdx.x;
    int tile = blockIdx.x;                // 0..255
    int b    = blockIdx.y;                // 0..3
    int z    = blockIdx.z;                // 0..1

    const float* f = (z ? f2 : f1) + (size_t)b * C * HW + tile * 256;
    const float* S = d_S[z][b];

    for (int i = tid; i < 4096; i += 256) { float s = S[i]; sS[i] = make_float2(s, s); }
    if (tid < 64) sw[tid] = d_wv[z][b][tid];

    #pragma unroll
    for (int it = 0; it < 16; it++) {
        int lin = tid + it * 256;          // float4 index 0..4095
        int c = lin >> 6, c4 = lin & 63;
        float4 v = *(const float4*)(f + (size_t)c * HW + c4 * 4);
        *(float4*)(sF + c * 256 + c4 * 4) = v;
    }
    __syncthreads();

    int pxg = tid & 63, ig = tid >> 6;
    int pA = 2 * pxg, pB = 128 + 2 * pxg;  // conflict-friendly pixel mapping

    float2 acc[16][2];
    #pragma unroll
    for (int ii = 0; ii < 16; ii++) {
        acc[ii][0] = make_float2(0.f, 0.f);
        acc[ii][1] = make_float2(0.f, 0.f);
    }
    const float2* srow = sS + ig * 16 * 64;
    for (int k = 0; k < 64; k++) {
        float2 fa = *(float2*)(sF + k * 256 + pA);
        float2 fb = *(float2*)(sF + k * 256 + pB);
        #pragma unroll
        for (int ii = 0; ii < 16; ii++) {
            float2 s2 = srow[ii * 64 + k];
            acc[ii][0] = ffma2(s2, fa, acc[ii][0]);
            acc[ii][1] = ffma2(s2, fb, acc[ii][1]);
        }
    }
    // partial max over this thread's 16 channels
    float2 mA = acc[0][0], mB = acc[0][1];
    #pragma unroll
    for (int ii = 1; ii < 16; ii++) {
        mA.x = fmaxf(mA.x, acc[ii][0].x); mA.y = fmaxf(mA.y, acc[ii][0].y);
        mB.x = fmaxf(mB.x, acc[ii][1].x); mB.y = fmaxf(mB.y, acc[ii][1].y);
    }
    *(float4*)(red + (ig * 64 + pxg) * 4) = make_float4(mA.x, mA.y, mB.x, mB.y);
    __syncthreads();

    if (ig == 0) {
        float4 m = *(float4*)(red + pxg * 4);
        #pragma unroll
        for (int g2 = 1; g2 < 4; g2++) {
            float4 o = *(float4*)(red + (g2 * 64 + pxg) * 4);
            m.x = fmaxf(m.x, o.x); m.y = fmaxf(m.y, o.y);
            m.z = fmaxf(m.z, o.z); m.w = fmaxf(m.w, o.w);
        }
        // mean_i(S@f) = (mean_i S) @ f = w . f
        float4 mn = make_float4(0.f, 0.f, 0.f, 0.f);
        for (int k = 0; k < 64; k++) {
            float wk = sw[k];
            const float* r = sF + k * 256;
            mn.x += wk * r[pA]; mn.y += wk * r[pA + 1];
            mn.z += wk * r[pB]; mn.w += wk * r[pB + 1];
        }
        float* pm = &d_pooled[z][b][0][tile * 256];
        float* px = &d_pooled[z][b][1][tile * 256];
        pm[pA] = mn.x; pm[pA + 1] = mn.y; pm[pB] = mn.z; pm[pB + 1] = mn.w;
        px[pA] = m.x;  px[pA + 1] = m.y;  px[pB] = m.z;  px[pB + 1] = m.w;
    }
}

// ---------------- kernel 4/5: 3x3 convs (SAME, cross-correlation) ----------
__global__ void conv1_kernel(const float* __restrict__ cw,
                             const float* __restrict__ cb) {
    int tid = threadIdx.x;
    int pix = blockIdx.x * 256 + tid;
    int zb = blockIdx.y; int z = zb >> 2, b = zb & 3;
    int y = pix >> 8, x = pix & 255;
    const float* p0 = d_pooled[z][b][0];
    const float* p1 = d_pooled[z][b][1];
    float acc = cb[0];
    #pragma unroll
    for (int dy = -1; dy <= 1; dy++) {
        int yy = y + dy;
        if (yy < 0 || yy > 255) continue;
        #pragma unroll
        for (int dx = -1; dx <= 1; dx++) {
            int xx = x + dx;
            if (xx < 0 || xx > 255) continue;
            int q = yy * 256 + xx;
            int wi = (dy + 1) * 3 + (dx + 1);
            acc += cw[wi] * p0[q] + cw[9 + wi] * p1[q];
        }
    }
    d_t1[z][b][pix] = fmaxf(acc, 0.f);
}

__global__ void conv2_kernel(const float* __restrict__ cw,
                             const float* __restrict__ cb) {
    int tid = threadIdx.x;
    int pix = blockIdx.x * 256 + tid;
    int zb = blockIdx.y; int z = zb >> 2, b = zb & 3;
    int y = pix >> 8, x = pix & 255;
    const float* p0 = d_t1[z][b];
    float acc = cb[0];
    #pragma unroll
    for (int dy = -1; dy <= 1; dy++) {
        int yy = y + dy;
        if (yy < 0 || yy > 255) continue;
        #pragma unroll
        for (int dx = -1; dx <= 1; dx++) {
            int xx = x + dx;
            if (xx < 0 || xx > 255) continue;
            acc += cw[(dy + 1) * 3 + (dx + 1)] * p0[yy * 256 + xx];
        }
    }
    d_t2[z][b][pix] = acc;
}

// ---------------- kernel 6: softmax stats over HW per (z,b) ----------------
__global__ void softstat_kernel() {
    __shared__ float sred[1024];
    int tid = threadIdx.x;
    int z = blockIdx.x >> 2, b = blockIdx.x & 3;
    const float* yv = d_t2[z][b];
    float m = -INFINITY;
    for (int i = tid; i < HW; i += 1024) m = fmaxf(m, yv[i]);
    sred[tid] = m;
    __syncthreads();
    for (int o = 512; o > 0; o >>= 1) {
        if (tid < o) sred[tid] = fmaxf(sred[tid], sred[tid + o]);
        __syncthreads();
    }
    float M = sred[0];
    __syncthreads();
    float s = 0.f;
    for (int i = tid; i < HW; i += 1024) s += __expf(yv[i] - M);
    sred[tid] = s;
    __syncthreads();
    for (int o = 512; o > 0; o >>= 1) {
        if (tid < o) sred[tid] += sred[tid + o];
        __syncthreads();
    }
    if (tid == 0) { d_smax[z][b] = M; d_ssum[z][b] = sred[0]; }
}

// ---------------- kernel 7: o = f * (1 + g), g = softmax(y) broadcast ------
__global__ void out_kernel(const float* __restrict__ f1,
                           const float* __restrict__ f2,
                           float* __restrict__ out) {
    unsigned idx  = blockIdx.x * 256u + threadIdx.x;  // float4 index < 2^23
    unsigned pix4 = idx & 16383u;
    unsigned c    = (idx >> 14) & 63u;
    unsigned b    = (idx >> 20) & 3u;
    unsigned z    = idx >> 22;
    const float* f = z ? f2 : f1;
    float M    = d_smax[z][b];
    float rinv = 1.f / d_ssum[z][b];
    float4 yv = *(const float4*)(&d_t2[z][b][pix4 * 4]);
    float4 g;
    g.x = __expf(yv.x - M) * rinv;
    g.y = __expf(yv.y - M) * rinv;
    g.z = __expf(yv.z - M) * rinv;
    g.w = __expf(yv.w - M) * rinv;
    size_t base = ((size_t)(b * 64u + c)) * HW + pix4 * 4u;
    float4 v = *(const float4*)(f + base);
    float4 o;
    o.x = v.x + v.x * g.x;
    o.y = v.y + v.y * g.y;
    o.z = v.z + v.z * g.z;
    o.w = v.w + v.w * g.w;
    *(float4*)(out + (size_t)z * ((size_t)B * C * HW) + base) = o;
}

// ---------------- launch ----------------------------------------------------
extern "C" void kernel_launch(void* const* d_in, const int* in_sizes, int n_in,
                              void* d_out, int out_size) {
    const float* f1 = (const float*)d_in[0];
    const float* f2 = (const float*)d_in[1];

    cudaFuncSetAttribute(atpool_kernel,
                         cudaFuncAttributeMaxDynamicSharedMemorySize,
                         ATP_SMEM_FLOATS * (int)sizeof(float));

    stats_kernel<<<512, 256>>>(f1, f2);

    mlp_kernel<<<1, 256>>>(
        (const float*)d_in[2],  (const float*)d_in[3],   // w_avg1,  b_avg1
        (const float*)d_in[4],  (const float*)d_in[5],   // w_max1,  b_max1
        (const float*)d_in[6],  (const float*)d_in[7],   // w_avg11, b_avg11
        (const float*)d_in[8],  (const float*)d_in[9],   // w_max11, b_max11
        (const float*)d_in[10], (const float*)d_in[11],  // w_avg2,  b_avg2
        (const float*)d_in[12], (const float*)d_in[13],  // w_max2,  b_max2
        (const float*)d_in[14], (const float*)d_in[15],  // w_avg22, b_avg22
        (const float*)d_in[16], (const float*)d_in[17]); // w_max22, b_max22

    atpool_kernel<<<dim3(256, 4, 2), 256,
                    ATP_SMEM_FLOATS * (int)sizeof(float)>>>(f1, f2);

    conv1_kernel<<<dim3(256, 8), 256>>>((const float*)d_in[18], (const float*)d_in[19]);
    conv2_kernel<<<dim3(256, 8), 256>>>((const float*)d_in[20], (const float*)d_in[21]);

    softstat_kernel<<<8, 1024>>>();

    out_kernel<<<32768, 256>>>(f1, f2, (float*)d_out);
}

// round 2
// speedup vs baseline: 1.0777x; 1.0777x over previous
#include <cuda_runtime.h>
#include <cuda_bf16.h>
#include <math.h>
#include <stdint.h>

#define B  4
#define C  64
#define CR 32
#define HW 65536

// ---------------- scratch (device globals; no allocation allowed) ----------
__device__ float d_avg[2][B][C];
__device__ float d_mx [2][B][C];
__device__ float d_S  [2][B][C*C];            // S (row-softmaxed, fp32)
__device__ __nv_bfloat16 d_Sb[2][B][C*C];     // S bf16 row-major [i][k]
__device__ float d_wv [2][B][C];              // column means of S
__device__ float d_pooled[2][B][2][HW];       // [z][b][{mean,max}][pix]
__device__ float d_t1[2][B][HW];
__device__ float d_t2[2][B][HW];
__device__ float d_smax[2][B];
__device__ float d_ssum[2][B];

// ---------------- small PTX helpers ----------------------------------------
__device__ __forceinline__ uint32_t pack_bf16(float lo, float hi) {
    uint32_t d;
    asm("cvt.rn.bf16x2.f32 %0, %1, %2;" : "=r"(d) : "f"(hi), "f"(lo));
    return d;
}

__device__ __forceinline__ void ldsm_x4(uint32_t r[4], uint32_t addr) {
    asm volatile("ldmatrix.sync.aligned.m8n8.x4.shared.b16 {%0,%1,%2,%3}, [%4];"
                 : "=r"(r[0]), "=r"(r[1]), "=r"(r[2]), "=r"(r[3]) : "r"(addr));
}

__device__ __forceinline__ void ldsm_x4_trans(uint32_t r[4], uint32_t addr) {
    asm volatile("ldmatrix.sync.aligned.m8n8.x4.trans.shared.b16 {%0,%1,%2,%3}, [%4];"
                 : "=r"(r[0]), "=r"(r[1]), "=r"(r[2]), "=r"(r[3]) : "r"(addr));
}

__device__ __forceinline__ void mma_bf16(float d[4], const uint32_t a[4],
                                         uint32_t b0, uint32_t b1) {
    asm volatile(
        "mma.sync.aligned.m16n8k16.row.col.f32.bf16.bf16.f32 "
        "{%0,%1,%2,%3}, {%4,%5,%6,%7}, {%8,%9}, {%0,%1,%2,%3};"
        : "+f"(d[0]), "+f"(d[1]), "+f"(d[2]), "+f"(d[3])
        : "r"(a[0]), "r"(a[1]), "r"(a[2]), "r"(a[3]), "r"(b0), "r"(b1));
}

// ---------------- kernel 1: per-(input,b,c) mean & max over HW -------------
__global__ void stats_kernel(const float* __restrict__ f1,
                             const float* __restrict__ f2) {
    int row = blockIdx.x;            // 0..511
    int z   = row >> 8;
    int idx = row & 255;             // b*64 + c
    const float* f = (z ? f2 : f1) + (size_t)idx * HW;
    int tid = threadIdx.x;

    float s = 0.f, m = -INFINITY;
    const float4* f4 = (const float4*)f;
    for (int i = tid; i < HW / 4; i += 256) {
        float4 v = f4[i];
        s += (v.x + v.y) + (v.z + v.w);
        m = fmaxf(m, fmaxf(fmaxf(v.x, v.y), fmaxf(v.z, v.w)));
    }
    __shared__ float ss[256], sm[256];
    ss[tid] = s; sm[tid] = m;
    __syncthreads();
    for (int o = 128; o > 0; o >>= 1) {
        if (tid < o) { ss[tid] += ss[tid + o]; sm[tid] = fmaxf(sm[tid], sm[tid + o]); }
        __syncthreads();
    }
    if (tid == 0) {
        d_avg[z][idx >> 6][idx & 63] = ss[0] * (1.f / HW);
        d_mx [z][idx >> 6][idx & 63] = sm[0];
    }
}

// ---------------- kernel 2: MLPs + rank-1 cross softmax --------------------
__global__ void mlp_kernel(
    const float* __restrict__ w_a1,  const float* __restrict__ b_a1,
    const float* __restrict__ w_m1,  const float* __restrict__ b_m1,
    const float* __restrict__ w_a11, const float* __restrict__ b_a11,
    const float* __restrict__ w_m11, const float* __restrict__ b_m11,
    const float* __restrict__ w_a2,  const float* __restrict__ b_a2,
    const float* __restrict__ w_m2,  const float* __restrict__ b_m2,
    const float* __restrict__ w_a22, const float* __restrict__ b_a22,
    const float* __restrict__ w_m22, const float* __restrict__ b_m22)
{
    __shared__ float s_stat[4][B][C];
    __shared__ float s_hid [4][B][CR];
    __shared__ float s_a   [2][B][C];
    int tid = threadIdx.x;

    { // stage stats
        int b = tid >> 6, c = tid & 63;
        s_stat[0][b][c] = d_avg[0][b][c];
        s_stat[1][b][c] = d_mx [0][b][c];
        s_stat[2][b][c] = d_avg[1][b][c];
        s_stat[3][b][c] = d_mx [1][b][c];
    }
    __syncthreads();

    const float* Wp[4] = {w_a1, w_m1, w_a2, w_m2};
    const float* Bp[4] = {b_a1, b_m1, b_a2, b_m2};
    for (int e = tid; e < 4 * B * CR; e += 256) {
        int p = e >> 7, b = (e >> 5) & 3, k = e & 31;
        const float* wr = Wp[p] + k * C;
        float acc = Bp[p][k];
        #pragma unroll 8
        for (int c2 = 0; c2 < C; c2++) acc += s_stat[p][b][c2] * wr[c2];
        s_hid[p][b][k] = fmaxf(acc, 0.f);
    }
    __syncthreads();

    {
        int b = tid >> 6, i = tid & 63;
        float a1 = b_a11[i] + b_m11[i];
        float a2 = b_a22[i] + b_m22[i];
        #pragma unroll 8
        for (int k = 0; k < CR; k++) {
            a1 += s_hid[0][b][k] * w_a11[i * CR + k] + s_hid[1][b][k] * w_m11[i * CR + k];
            a2 += s_hid[2][b][k] * w_a22[i * CR + k] + s_hid[3][b][k] * w_m22[i * CR + k];
        }
        s_a[0][b][i] = a1;
        s_a[1][b][i] = a2;
    }
    __syncthreads();

    { // S rows = softmax_j(a_zz[i] * a_other[j]); also emit bf16 copy
        int b = tid >> 6, i = tid & 63;
        for (int zz = 0; zz < 2; zz++) {
            float x = s_a[zz][b][i];
            const float* other = s_a[1 - zz][b];
            float m = -INFINITY;
            for (int j = 0; j < C; j++) m = fmaxf(m, x * other[j]);
            float* Srow = &d_S[zz][b][i * C];
            float Z = 0.f;
            for (int j = 0; j < C; j++) {
                float e2 = __expf(x * other[j] - m);
                Srow[j] = e2;
                Z += e2;
            }
            float inv = 1.f / Z;
            for (int j = 0; j < C; j++) {
                float v = Srow[j] * inv;
                Srow[j] = v;
                d_Sb[zz][b][i * C + j] = __float2bfloat16(v);
            }
        }
    }
    __syncthreads();

    { // wv = column means of S
        int b = tid >> 6, j = tid & 63;
        for (int zz = 0; zz < 2; zz++) {
            float s = 0.f;
            for (int i2 = 0; i2 < C; i2++) s += d_S[zz][b][i2 * C + j];
            d_wv[zz][b][j] = s * (1.f / C);
        }
    }
}

// ---------------- kernel 3: attention pooling via bf16 HMMA ----------------
// Per (z,b,tile of 256 px): D[64 i, 256 px] = S @ F, emit max_i and w.f (mean).
#define PXT  256
#define FROW 264   // F smem row stride (px dim), pad for LDSM bank spread
#define SROW 72    // S smem row stride (k dim)
#define ATP_SMEM_BYTES (64*FROW*2 + 64*SROW*2 + 64*4)

__global__ void __launch_bounds__(256, 2)
atpool_kernel(const float* __restrict__ f1, const float* __restrict__ f2) {
    extern __shared__ char smraw[];
    __nv_bfloat16* sF = (__nv_bfloat16*)smraw;        // [64][FROW]
    __nv_bfloat16* sS = sF + 64 * FROW;               // [64][SROW]
    float* sw = (float*)(sS + 64 * SROW);             // [64]

    int tid = threadIdx.x, warp = tid >> 5, lane = tid & 31;
    int tile = blockIdx.x, b = blockIdx.y, z = blockIdx.z;
    const float* f = (z ? f2 : f1) + (size_t)b * C * HW + tile * PXT;
    const __nv_bfloat16* Sg = d_Sb[z][b];

    for (int i = tid; i < C * C; i += 256)
        sS[(i >> 6) * SROW + (i & 63)] = Sg[i];
    if (tid < 64) sw[tid] = d_wv[z][b][tid];

    // load F tile fp32 -> bf16 smem [k][px]
    #pragma unroll
    for (int it = 0; it < 16; it++) {
        int lin = tid + it * 256;            // 0..4095 float4 units
        int c = lin >> 6, p4 = (lin & 63) * 4;
        float4 v = *(const float4*)(f + (size_t)c * HW + p4);
        uint32_t u0 = pack_bf16(v.x, v.y);
        uint32_t u1 = pack_bf16(v.z, v.w);
        *(uint2*)(sF + c * FROW + p4) = make_uint2(u0, u1);
    }
    __syncthreads();

    int pxw = warp * 32;                     // this warp's 32 pixels
    float acc[4][4][4];
    #pragma unroll
    for (int mt = 0; mt < 4; mt++)
        #pragma unroll
        for (int nt = 0; nt < 4; nt++)
            #pragma unroll
            for (int r = 0; r < 4; r++) acc[mt][nt][r] = 0.f;

    #pragma unroll
    for (int kt = 0; kt < 4; kt++) {
        uint32_t a[4][4];
        #pragma unroll
        for (int mt = 0; mt < 4; mt++) {
            int row = mt * 16 + (lane & 15);
            int col = kt * 16 + ((lane & 16) ? 8 : 0);
            uint32_t ad = (uint32_t)__cvta_generic_to_shared(sS + row * SROW + col);
            ldsm_x4(a[mt], ad);
        }
        uint32_t bfr[2][4];
        #pragma unroll
        for (int h = 0; h < 2; h++) {
            int krow = kt * 16 + (lane & 7) + ((lane & 8) ? 8 : 0);
            int px   = pxw + h * 16 + ((lane & 16) ? 8 : 0);
            uint32_t ad = (uint32_t)__cvta_generic_to_shared(sF + krow * FROW + px);
            ldsm_x4_trans(bfr[h], ad);
        }
        #pragma unroll
        for (int mt = 0; mt < 4; mt++)
            #pragma unroll
            for (int nt = 0; nt < 4; nt++)
                mma_bf16(acc[mt][nt], a[mt],
                         bfr[nt >> 1][(nt & 1) * 2 + 0],
                         bfr[nt >> 1][(nt & 1) * 2 + 1]);
    }

    // ---- max over 64 channels ----
    float* pmax = &d_pooled[z][b][1][tile * PXT];
    #pragma unroll
    for (int nt = 0; nt < 4; nt++) {
        float m0 = fmaxf(fmaxf(acc[0][nt][0], acc[0][nt][2]),
                         fmaxf(acc[1][nt][0], acc[1][nt][2]));
        m0 = fmaxf(m0, fmaxf(fmaxf(acc[2][nt][0], acc[2][nt][2]),
                             fmaxf(acc[3][nt][0], acc[3][nt][2])));
        float m1 = fmaxf(fmaxf(acc[0][nt][1], acc[0][nt][3]),
                         fmaxf(acc[1][nt][1], acc[1][nt][3]));
        m1 = fmaxf(m1, fmaxf(fmaxf(acc[2][nt][1], acc[2][nt][3]),
                             fmaxf(acc[3][nt][1], acc[3][nt][3])));
        #pragma unroll
        for (int off = 4; off < 32; off <<= 1) {
            m0 = fmaxf(m0, __shfl_xor_sync(0xffffffffu, m0, off));
            m1 = fmaxf(m1, __shfl_xor_sync(0xffffffffu, m1, off));
        }
        if (lane < 4) {
            int px = pxw + nt * 8 + lane * 2;
            pmax[px]     = m0;
            pmax[px + 1] = m1;
        }
    }

    // ---- mean: w . f ----
    float s = 0.f;
    const __nv_bfloat16* colp = sF + pxw + lane;
    #pragma unroll 16
    for (int k = 0; k < 64; k++)
        s += sw[k] * __bfloat162float(colp[k * FROW]);
    d_pooled[z][b][0][tile * PXT + pxw + lane] = s;
}

// ---------------- kernel 4/5: 3x3 convs (SAME) -----------------------------
__global__ void conv1_kernel(const float* __restrict__ cw,
                             const float* __restrict__ cb) {
    int tid = threadIdx.x;
    int pix = blockIdx.x * 256 + tid;
    int zb = blockIdx.y; int z = zb >> 2, b = zb & 3;
    int y = pix >> 8, x = pix & 255;
    const float* p0 = d_pooled[z][b][0];
    const float* p1 = d_pooled[z][b][1];
    float acc = cb[0];
    #pragma unroll
    for (int dy = -1; dy <= 1; dy++) {
        int yy = y + dy;
        if (yy < 0 || yy > 255) continue;
        #pragma unroll
        for (int dx = -1; dx <= 1; dx++) {
            int xx = x + dx;
            if (xx < 0 || xx > 255) continue;
            int q = yy * 256 + xx;
            int wi = (dy + 1) * 3 + (dx + 1);
            acc += cw[wi] * p0[q] + cw[9 + wi] * p1[q];
        }
    }
    d_t1[z][b][pix] = fmaxf(acc, 0.f);
}

__global__ void conv2_kernel(const float* __restrict__ cw,
                             const float* __restrict__ cb) {
    int tid = threadIdx.x;
    int pix = blockIdx.x * 256 + tid;
    int zb = blockIdx.y; int z = zb >> 2, b = zb & 3;
    int y = pix >> 8, x = pix & 255;
    const float* p0 = d_t1[z][b];
    float acc = cb[0];
    #pragma unroll
    for (int dy = -1; dy <= 1; dy++) {
        int yy = y + dy;
        if (yy < 0 || yy > 255) continue;
        #pragma unroll
        for (int dx = -1; dx <= 1; dx++) {
            int xx = x + dx;
            if (xx < 0 || xx > 255) continue;
            acc += cw[(dy + 1) * 3 + (dx + 1)] * p0[yy * 256 + xx];
        }
    }
    d_t2[z][b][pix] = acc;
}

// ---------------- kernel 6: softmax stats over HW per (z,b) ----------------
__global__ void softstat_kernel() {
    __shared__ float sred[1024];
    int tid = threadIdx.x;
    int z = blockIdx.x >> 2, b = blockIdx.x & 3;
    const float* yv = d_t2[z][b];
    float m = -INFINITY;
    for (int i = tid; i < HW; i += 1024) m = fmaxf(m, yv[i]);
    sred[tid] = m;
    __syncthreads();
    for (int o = 512; o > 0; o >>= 1) {
        if (tid < o) sred[tid] = fmaxf(sred[tid], sred[tid + o]);
        __syncthreads();
    }
    float M = sred[0];
    __syncthreads();
    float s = 0.f;
    for (int i = tid; i < HW; i += 1024) s += __expf(yv[i] - M);
    sred[tid] = s;
    __syncthreads();
    for (int o = 512; o > 0; o >>= 1) {
        if (tid < o) sred[tid] += sred[tid + o];
        __syncthreads();
    }
    if (tid == 0) { d_smax[z][b] = M; d_ssum[z][b] = sred[0]; }
}

// ---------------- kernel 7: o = f * (1 + g) --------------------------------
__global__ void out_kernel(const float* __restrict__ f1,
                           const float* __restrict__ f2,
                           float* __restrict__ out) {
    unsigned idx  = blockIdx.x * 256u + threadIdx.x;
    unsigned pix4 = idx & 16383u;
    unsigned c    = (idx >> 14) & 63u;
    unsigned b    = (idx >> 20) & 3u;
    unsigned z    = idx >> 22;
    const float* f = z ? f2 : f1;
    float M    = d_smax[z][b];
    float rinv = 1.f / d_ssum[z][b];
    float4 yv = *(const float4*)(&d_t2[z][b][pix4 * 4]);
    float4 g;
    g.x = __expf(yv.x - M) * rinv;
    g.y = __expf(yv.y - M) * rinv;
    g.z = __expf(yv.z - M) * rinv;
    g.w = __expf(yv.w - M) * rinv;
    size_t base = ((size_t)(b * 64u + c)) * HW + pix4 * 4u;
    float4 v = *(const float4*)(f + base);
    float4 o;
    o.x = v.x + v.x * g.x;
    o.y = v.y + v.y * g.y;
    o.z = v.z + v.z * g.z;
    o.w = v.w + v.w * g.w;
    *(float4*)(out + (size_t)z * ((size_t)B * C * HW) + base) = o;
}

// ---------------- launch ----------------------------------------------------
extern "C" void kernel_launch(void* const* d_in, const int* in_sizes, int n_in,
                              void* d_out, int out_size) {
    const float* f1 = (const float*)d_in[0];
    const float* f2 = (const float*)d_in[1];

    cudaFuncSetAttribute(atpool_kernel,
                         cudaFuncAttributeMaxDynamicSharedMemorySize,
                         ATP_SMEM_BYTES);

    stats_kernel<<<512, 256>>>(f1, f2);

    mlp_kernel<<<1, 256>>>(
        (const float*)d_in[2],  (const float*)d_in[3],
        (const float*)d_in[4],  (const float*)d_in[5],
        (const float*)d_in[6],  (const float*)d_in[7],
        (const float*)d_in[8],  (const float*)d_in[9],
        (const float*)d_in[10], (const float*)d_in[11],
        (const float*)d_in[12], (const float*)d_in[13],
        (const float*)d_in[14], (const float*)d_in[15],
        (const float*)d_in[16], (const float*)d_in[17]);

    atpool_kernel<<<dim3(256, 4, 2), 256, ATP_SMEM_BYTES>>>(f1, f2);

    conv1_kernel<<<dim3(256, 8), 256>>>((const float*)d_in[18], (const float*)d_in[19]);
    conv2_kernel<<<dim3(256, 8), 256>>>((const float*)d_in[20], (const float*)d_in[21]);

    softstat_kernel<<<8, 1024>>>();

    out_kernel<<<32768, 256>>>(f1, f2, (float*)d_out);
}

// round 3
// speedup vs baseline: 1.1119x; 1.0318x over previous
#include <cuda_runtime.h>
#include <cuda_bf16.h>
#include <math.h>
#include <stdint.h>

#define B  4
#define C  64
#define CR 32
#define HW 65536

// ---------------- scratch (device globals; no allocation allowed) ----------
__device__ float d_avg[2][B][C];
__device__ float d_mx [2][B][C];
__device__ float d_S  [2][B][C*C];            // S (row-softmaxed, fp32)
__device__ __nv_bfloat16 d_Sb[2][B][C*C];     // S bf16 row-major [i][k]
__device__ float d_wv [2][B][C];              // column means of S
__device__ float d_pooled[2][B][2][HW];       // [z][b][{mean,max}][pix]
__device__ float d_t1[2][B][HW];
__device__ float d_t2[2][B][HW];
__device__ float d_g [2][B][HW];              // materialized gate
__device__ float d_smax[2][B];
__device__ float d_ssum[2][B];

// ---------------- small PTX helpers ----------------------------------------
__device__ __forceinline__ uint32_t pack_bf16(float lo, float hi) {
    uint32_t d;
    asm("cvt.rn.bf16x2.f32 %0, %1, %2;" : "=r"(d) : "f"(hi), "f"(lo));
    return d;
}

__device__ __forceinline__ void ldsm_x4(uint32_t r[4], uint32_t addr) {
    asm volatile("ldmatrix.sync.aligned.m8n8.x4.shared.b16 {%0,%1,%2,%3}, [%4];"
                 : "=r"(r[0]), "=r"(r[1]), "=r"(r[2]), "=r"(r[3]) : "r"(addr));
}

__device__ __forceinline__ void ldsm_x4_trans(uint32_t r[4], uint32_t addr) {
    asm volatile("ldmatrix.sync.aligned.m8n8.x4.trans.shared.b16 {%0,%1,%2,%3}, [%4];"
                 : "=r"(r[0]), "=r"(r[1]), "=r"(r[2]), "=r"(r[3]) : "r"(addr));
}

__device__ __forceinline__ void mma_bf16(float d[4], const uint32_t a[4],
                                         uint32_t b0, uint32_t b1) {
    asm volatile(
        "mma.sync.aligned.m16n8k16.row.col.f32.bf16.bf16.f32 "
        "{%0,%1,%2,%3}, {%4,%5,%6,%7}, {%8,%9}, {%0,%1,%2,%3};"
        : "+f"(d[0]), "+f"(d[1]), "+f"(d[2]), "+f"(d[3])
        : "r"(a[0]), "r"(a[1]), "r"(a[2]), "r"(a[3]), "r"(b0), "r"(b1));
}

// ---------------- kernel 1: per-(input,b,c) mean & max over HW -------------
__global__ void stats_kernel(const float* __restrict__ f1,
                             const float* __restrict__ f2) {
    int row = blockIdx.x;            // 0..511
    int z   = row >> 8;
    int idx = row & 255;             // b*64 + c
    const float* f = (z ? f2 : f1) + (size_t)idx * HW;
    int tid = threadIdx.x;

    float s = 0.f, m = -INFINITY;
    const float4* f4 = (const float4*)f;
    #pragma unroll 8
    for (int i = tid; i < HW / 4; i += 256) {
        float4 v = f4[i];
        s += (v.x + v.y) + (v.z + v.w);
        m = fmaxf(m, fmaxf(fmaxf(v.x, v.y), fmaxf(v.z, v.w)));
    }
    __shared__ float ss[256], sm[256];
    ss[tid] = s; sm[tid] = m;
    __syncthreads();
    for (int o = 128; o > 0; o >>= 1) {
        if (tid < o) { ss[tid] += ss[tid + o]; sm[tid] = fmaxf(sm[tid], sm[tid + o]); }
        __syncthreads();
    }
    if (tid == 0) {
        d_avg[z][idx >> 6][idx & 63] = ss[0] * (1.f / HW);
        d_mx [z][idx >> 6][idx & 63] = sm[0];
    }
}

// ---------------- kernel 2: MLPs + rank-1 cross softmax --------------------
__global__ void mlp_kernel(
    const float* __restrict__ w_a1,  const float* __restrict__ b_a1,
    const float* __restrict__ w_m1,  const float* __restrict__ b_m1,
    const float* __restrict__ w_a11, const float* __restrict__ b_a11,
    const float* __restrict__ w_m11, const float* __restrict__ b_m11,
    const float* __restrict__ w_a2,  const float* __restrict__ b_a2,
    const float* __restrict__ w_m2,  const float* __restrict__ b_m2,
    const float* __restrict__ w_a22, const float* __restrict__ b_a22,
    const float* __restrict__ w_m22, const float* __restrict__ b_m22)
{
    __shared__ float s_stat[4][B][C];
    __shared__ float s_hid [4][B][CR];
    __shared__ float s_a   [2][B][C];
    int tid = threadIdx.x;

    {
        int b = tid >> 6, c = tid & 63;
        s_stat[0][b][c] = d_avg[0][b][c];
        s_stat[1][b][c] = d_mx [0][b][c];
        s_stat[2][b][c] = d_avg[1][b][c];
        s_stat[3][b][c] = d_mx [1][b][c];
    }
    __syncthreads();

    const float* Wp[4] = {w_a1, w_m1, w_a2, w_m2};
    const float* Bp[4] = {b_a1, b_m1, b_a2, b_m2};
    for (int e = tid; e < 4 * B * CR; e += 256) {
        int p = e >> 7, b = (e >> 5) & 3, k = e & 31;
        const float* wr = Wp[p] + k * C;
        float acc = Bp[p][k];
        #pragma unroll 8
        for (int c2 = 0; c2 < C; c2++) acc += s_stat[p][b][c2] * wr[c2];
        s_hid[p][b][k] = fmaxf(acc, 0.f);
    }
    __syncthreads();

    {
        int b = tid >> 6, i = tid & 63;
        float a1 = b_a11[i] + b_m11[i];
        float a2 = b_a22[i] + b_m22[i];
        #pragma unroll 8
        for (int k = 0; k < CR; k++) {
            a1 += s_hid[0][b][k] * w_a11[i * CR + k] + s_hid[1][b][k] * w_m11[i * CR + k];
            a2 += s_hid[2][b][k] * w_a22[i * CR + k] + s_hid[3][b][k] * w_m22[i * CR + k];
        }
        s_a[0][b][i] = a1;
        s_a[1][b][i] = a2;
    }
    __syncthreads();

    {
        int b = tid >> 6, i = tid & 63;
        for (int zz = 0; zz < 2; zz++) {
            float x = s_a[zz][b][i];
            const float* other = s_a[1 - zz][b];
            float m = -INFINITY;
            for (int j = 0; j < C; j++) m = fmaxf(m, x * other[j]);
            float* Srow = &d_S[zz][b][i * C];
            float Z = 0.f;
            for (int j = 0; j < C; j++) {
                float e2 = __expf(x * other[j] - m);
                Srow[j] = e2;
                Z += e2;
            }
            float inv = 1.f / Z;
            for (int j = 0; j < C; j++) {
                float v = Srow[j] * inv;
                Srow[j] = v;
                d_Sb[zz][b][i * C + j] = __float2bfloat16(v);
            }
        }
    }
    __syncthreads();

    {
        int b = tid >> 6, j = tid & 63;
        for (int zz = 0; zz < 2; zz++) {
            float s = 0.f;
            for (int i2 = 0; i2 < C; i2++) s += d_S[zz][b][i2 * C + j];
            d_wv[zz][b][j] = s * (1.f / C);
        }
    }
}

// ---------------- kernel 3: attention pooling via bf16 HMMA ----------------
#define PXT  256
#define FROW 264
#define SROW 72
#define ATP_SMEM_BYTES (64*FROW*2 + 64*SROW*2 + 64*4)

__global__ void __launch_bounds__(256, 2)
atpool_kernel(const float* __restrict__ f1, const float* __restrict__ f2) {
    extern __shared__ char smraw[];
    __nv_bfloat16* sF = (__nv_bfloat16*)smraw;        // [64][FROW]
    __nv_bfloat16* sS = sF + 64 * FROW;               // [64][SROW]
    float* sw = (float*)(sS + 64 * SROW);             // [64]

    int tid = threadIdx.x, warp = tid >> 5, lane = tid & 31;
    int tile = blockIdx.x, b = blockIdx.y, z = blockIdx.z;
    const float* f = (z ? f2 : f1) + (size_t)b * C * HW + tile * PXT;
    const __nv_bfloat16* Sg = d_Sb[z][b];

    for (int i = tid; i < C * C; i += 256)
        sS[(i >> 6) * SROW + (i & 63)] = Sg[i];
    if (tid < 64) sw[tid] = d_wv[z][b][tid];

    #pragma unroll
    for (int it = 0; it < 16; it++) {
        int lin = tid + it * 256;
        int c = lin >> 6, p4 = (lin & 63) * 4;
        float4 v = *(const float4*)(f + (size_t)c * HW + p4);
        uint32_t u0 = pack_bf16(v.x, v.y);
        uint32_t u1 = pack_bf16(v.z, v.w);
        *(uint2*)(sF + c * FROW + p4) = make_uint2(u0, u1);
    }
    __syncthreads();

    int pxw = warp * 32;
    float acc[4][4][4];
    #pragma unroll
    for (int mt = 0; mt < 4; mt++)
        #pragma unroll
        for (int nt = 0; nt < 4; nt++)
            #pragma unroll
            for (int r = 0; r < 4; r++) acc[mt][nt][r] = 0.f;

    #pragma unroll
    for (int kt = 0; kt < 4; kt++) {
        uint32_t a[4][4];
        #pragma unroll
        for (int mt = 0; mt < 4; mt++) {
            int row = mt * 16 + (lane & 15);
            int col = kt * 16 + ((lane & 16) ? 8 : 0);
            uint32_t ad = (uint32_t)__cvta_generic_to_shared(sS + row * SROW + col);
            ldsm_x4(a[mt], ad);
        }
        uint32_t bfr[2][4];
        #pragma unroll
        for (int h = 0; h < 2; h++) {
            int krow = kt * 16 + (lane & 15);
            int px   = pxw + h * 16 + ((lane & 16) ? 8 : 0);
            uint32_t ad = (uint32_t)__cvta_generic_to_shared(sF + krow * FROW + px);
            ldsm_x4_trans(bfr[h], ad);
        }
        #pragma unroll
        for (int mt = 0; mt < 4; mt++)
            #pragma unroll
            for (int nt = 0; nt < 4; nt++)
                mma_bf16(acc[mt][nt], a[mt],
                         bfr[nt >> 1][(nt & 1) * 2 + 0],
                         bfr[nt >> 1][(nt & 1) * 2 + 1]);
    }

    float* pmax = &d_pooled[z][b][1][tile * PXT];
    #pragma unroll
    for (int nt = 0; nt < 4; nt++) {
        float m0 = fmaxf(fmaxf(acc[0][nt][0], acc[0][nt][2]),
                         fmaxf(acc[1][nt][0], acc[1][nt][2]));
        m0 = fmaxf(m0, fmaxf(fmaxf(acc[2][nt][0], acc[2][nt][2]),
                             fmaxf(acc[3][nt][0], acc[3][nt][2])));
        float m1 = fmaxf(fmaxf(acc[0][nt][1], acc[0][nt][3]),
                         fmaxf(acc[1][nt][1], acc[1][nt][3]));
        m1 = fmaxf(m1, fmaxf(fmaxf(acc[2][nt][1], acc[2][nt][3]),
                             fmaxf(acc[3][nt][1], acc[3][nt][3])));
        #pragma unroll
        for (int off = 4; off < 32; off <<= 1) {
            m0 = fmaxf(m0, __shfl_xor_sync(0xffffffffu, m0, off));
            m1 = fmaxf(m1, __shfl_xor_sync(0xffffffffu, m1, off));
        }
        if (lane < 4) {
            int px = pxw + nt * 8 + lane * 2;
            pmax[px]     = m0;
            pmax[px + 1] = m1;
        }
    }

    float s = 0.f;
    const __nv_bfloat16* colp = sF + pxw + lane;
    #pragma unroll 16
    for (int k = 0; k < 64; k++)
        s += sw[k] * __bfloat162float(colp[k * FROW]);
    d_pooled[z][b][0][tile * PXT + pxw + lane] = s;
}

// ---------------- kernel 4/5: 3x3 convs (SAME) -----------------------------
__global__ void conv1_kernel(const float* __restrict__ cw,
                             const float* __restrict__ cb) {
    int tid = threadIdx.x;
    int pix = blockIdx.x * 256 + tid;
    int zb = blockIdx.y; int z = zb >> 2, b = zb & 3;
    int y = pix >> 8, x = pix & 255;
    const float* p0 = d_pooled[z][b][0];
    const float* p1 = d_pooled[z][b][1];
    float acc = cb[0];
    #pragma unroll
    for (int dy = -1; dy <= 1; dy++) {
        int yy = y + dy;
        if (yy < 0 || yy > 255) continue;
        #pragma unroll
        for (int dx = -1; dx <= 1; dx++) {
            int xx = x + dx;
            if (xx < 0 || xx > 255) continue;
            int q = yy * 256 + xx;
            int wi = (dy + 1) * 3 + (dx + 1);
            acc += cw[wi] * p0[q] + cw[9 + wi] * p1[q];
        }
    }
    d_t1[z][b][pix] = fmaxf(acc, 0.f);
}

__global__ void conv2_kernel(const float* __restrict__ cw,
                             const float* __restrict__ cb) {
    int tid = threadIdx.x;
    int pix = blockIdx.x * 256 + tid;
    int zb = blockIdx.y; int z = zb >> 2, b = zb & 3;
    int y = pix >> 8, x = pix & 255;
    const float* p0 = d_t1[z][b];
    float acc = cb[0];
    #pragma unroll
    for (int dy = -1; dy <= 1; dy++) {
        int yy = y + dy;
        if (yy < 0 || yy > 255) continue;
        #pragma unroll
        for (int dx = -1; dx <= 1; dx++) {
            int xx = x + dx;
            if (xx < 0 || xx > 255) continue;
            acc += cw[(dy + 1) * 3 + (dx + 1)] * p0[yy * 256 + xx];
        }
    }
    d_t2[z][b][pix] = acc;
}

// ---------------- kernel 6: softmax stats over HW per (z,b) ----------------
__global__ void softstat_kernel() {
    __shared__ float sred[1024];
    int tid = threadIdx.x;
    int z = blockIdx.x >> 2, b = blockIdx.x & 3;
    const float* yv = d_t2[z][b];
    float m = -INFINITY;
    for (int i = tid; i < HW; i += 1024) m = fmaxf(m, yv[i]);
    sred[tid] = m;
    __syncthreads();
    for (int o = 512; o > 0; o >>= 1) {
        if (tid < o) sred[tid] = fmaxf(sred[tid], sred[tid + o]);
        __syncthreads();
    }
    float M = sred[0];
    __syncthreads();
    float s = 0.f;
    for (int i = tid; i < HW; i += 1024) s += __expf(yv[i] - M);
    sred[tid] = s;
    __syncthreads();
    for (int o = 512; o > 0; o >>= 1) {
        if (tid < o) sred[tid] += sred[tid + o];
        __syncthreads();
    }
    if (tid == 0) { d_smax[z][b] = M; d_ssum[z][b] = sred[0]; }
}

// ---------------- kernel 6b: materialize gate g = exp(y-M)/sum -------------
__global__ void gate_kernel() {
    int zb = blockIdx.y; int z = zb >> 2, b = zb & 3;
    int i4 = blockIdx.x * 256 + threadIdx.x;   // float4 index, 16384 per zb
    float M    = d_smax[z][b];
    float rinv = 1.f / d_ssum[z][b];
    float4 yv = *(const float4*)(&d_t2[z][b][i4 * 4]);
    float4 g;
    g.x = __expf(yv.x - M) * rinv;
    g.y = __expf(yv.y - M) * rinv;
    g.z = __expf(yv.z - M) * rinv;
    g.w = __expf(yv.w - M) * rinv;
    *(float4*)(&d_g[z][b][i4 * 4]) = g;
}

// ---------------- kernel 7: o = f * (1 + g), pure streaming FMA ------------
__global__ void out_kernel(const float* __restrict__ f1,
                           const float* __restrict__ f2,
                           float* __restrict__ out) {
    unsigned idx  = blockIdx.x * 256u + threadIdx.x;
    unsigned pix4 = idx & 16383u;
    unsigned c    = (idx >> 14) & 63u;
    unsigned b    = (idx >> 20) & 3u;
    unsigned z    = idx >> 22;
    const float* f = z ? f2 : f1;
    float4 g = *(const float4*)(&d_g[z][b][pix4 * 4]);
    size_t base = ((size_t)(b * 64u + c)) * HW + pix4 * 4u;
    float4 v = *(const float4*)(f + base);
    float4 o;
    o.x = fmaf(v.x, g.x, v.x);
    o.y = fmaf(v.y, g.y, v.y);
    o.z = fmaf(v.z, g.z, v.z);
    o.w = fmaf(v.w, g.w, v.w);
    *(float4*)(out + (size_t)z * ((size_t)B * C * HW) + base) = o;
}

// ---------------- launch ----------------------------------------------------
extern "C" void kernel_launch(void* const* d_in, const int* in_sizes, int n_in,
                              void* d_out, int out_size) {
    const float* f1 = (const float*)d_in[0];
    const float* f2 = (const float*)d_in[1];

    cudaFuncSetAttribute(atpool_kernel,
                         cudaFuncAttributeMaxDynamicSharedMemorySize,
                         ATP_SMEM_BYTES);

    stats_kernel<<<512, 256>>>(f1, f2);

    mlp_kernel<<<1, 256>>>(
        (const float*)d_in[2],  (const float*)d_in[3],
        (const float*)d_in[4],  (const float*)d_in[5],
        (const float*)d_in[6],  (const float*)d_in[7],
        (const float*)d_in[8],  (const float*)d_in[9],
        (const float*)d_in[10], (const float*)d_in[11],
        (const float*)d_in[12], (const float*)d_in[13],
        (const float*)d_in[14], (const float*)d_in[15],
        (const float*)d_in[16], (const float*)d_in[17]);

    atpool_kernel<<<dim3(256, 4, 2), 256, ATP_SMEM_BYTES>>>(f1, f2);

    conv1_kernel<<<dim3(256, 8), 256>>>((const float*)d_in[18], (const float*)d_in[19]);
    conv2_kernel<<<dim3(256, 8), 256>>>((const float*)d_in[20], (const float*)d_in[21]);

    softstat_kernel<<<8, 1024>>>();

    gate_kernel<<<dim3(64, 8), 256>>>();

    out_kernel<<<32768, 256>>>(f1, f2, (float*)d_out);
}

// round 4
// speedup vs baseline: 1.1410x; 1.0261x over previous
#include <cuda_runtime.h>
#include <cuda_bf16.h>
#include <math.h>
#include <stdint.h>

#define B  4
#define C  64
#define CR 32
#define HW 65536

// ---------------- scratch (device globals) ----------------------------------
__device__ float d_ps[512][4];                // stats partial sums
__device__ float d_pm[512][4];                // stats partial maxes
__device__ float d_S  [2][B][C*C];
__device__ __nv_bfloat16 d_Sb[2][B][C*C];
__device__ float d_wv [2][B][C];
__device__ float d_pooled[2][B][2][HW];
__device__ float d_t2[2][B][HW];
__device__ float d_g [2][B][HW];
__device__ float d_smax[2][B];
__device__ float d_ssum[2][B];

// ---------------- PTX helpers ------------------------------------------------
__device__ __forceinline__ uint32_t pack_bf16(float lo, float hi) {
    uint32_t d;
    asm("cvt.rn.bf16x2.f32 %0, %1, %2;" : "=r"(d) : "f"(hi), "f"(lo));
    return d;
}
__device__ __forceinline__ void ldsm_x4(uint32_t r[4], uint32_t addr) {
    asm volatile("ldmatrix.sync.aligned.m8n8.x4.shared.b16 {%0,%1,%2,%3}, [%4];"
                 : "=r"(r[0]), "=r"(r[1]), "=r"(r[2]), "=r"(r[3]) : "r"(addr));
}
__device__ __forceinline__ void ldsm_x4_trans(uint32_t r[4], uint32_t addr) {
    asm volatile("ldmatrix.sync.aligned.m8n8.x4.trans.shared.b16 {%0,%1,%2,%3}, [%4];"
                 : "=r"(r[0]), "=r"(r[1]), "=r"(r[2]), "=r"(r[3]) : "r"(addr));
}
__device__ __forceinline__ void mma_bf16(float d[4], const uint32_t a[4],
                                         uint32_t b0, uint32_t b1) {
    asm volatile(
        "mma.sync.aligned.m16n8k16.row.col.f32.bf16.bf16.f32 "
        "{%0,%1,%2,%3}, {%4,%5,%6,%7}, {%8,%9}, {%0,%1,%2,%3};"
        : "+f"(d[0]), "+f"(d[1]), "+f"(d[2]), "+f"(d[3])
        : "r"(a[0]), "r"(a[1]), "r"(a[2]), "r"(a[3]), "r"(b0), "r"(b1));
}

// ---------------- kernel 1: stats partials (f2 first, f1 last for L2) -------
__global__ void stats_kernel(const float* __restrict__ f1,
                             const float* __restrict__ f2) {
    int lin   = blockIdx.x;              // 0..2047
    int row   = 511 - (lin >> 2);        // rows descending: f2 chunks first
    int chunk = lin & 3;
    const float* f = (row < 256) ? (f1 + (size_t)row * HW)
                                 : (f2 + (size_t)(row - 256) * HW);
    int tid = threadIdx.x;
    const float4* f4 = (const float4*)f + chunk * 4096;

    float s = 0.f, m = -INFINITY;
    #pragma unroll
    for (int k = 0; k < 16; k++) {
        float4 v = f4[tid + k * 256];
        s += (v.x + v.y) + (v.z + v.w);
        m = fmaxf(m, fmaxf(fmaxf(v.x, v.y), fmaxf(v.z, v.w)));
    }
    __shared__ float ss[256], sm[256];
    ss[tid] = s; sm[tid] = m;
    __syncthreads();
    for (int o = 128; o > 0; o >>= 1) {
        if (tid < o) { ss[tid] += ss[tid + o]; sm[tid] = fmaxf(sm[tid], sm[tid + o]); }
        __syncthreads();
    }
    if (tid == 0) { d_ps[row][chunk] = ss[0]; d_pm[row][chunk] = sm[0]; }
}

// ---------------- kernel 2: reduce partials + MLPs + rank-1 cross softmax ---
__global__ void mlp_kernel(
    const float* __restrict__ w_a1,  const float* __restrict__ b_a1,
    const float* __restrict__ w_m1,  const float* __restrict__ b_m1,
    const float* __restrict__ w_a11, const float* __restrict__ b_a11,
    const float* __restrict__ w_m11, const float* __restrict__ b_m11,
    const float* __restrict__ w_a2,  const float* __restrict__ b_a2,
    const float* __restrict__ w_m2,  const float* __restrict__ b_m2,
    const float* __restrict__ w_a22, const float* __restrict__ b_a22,
    const float* __restrict__ w_m22, const float* __restrict__ b_m22)
{
    __shared__ float s_stat[4][B][C];   // avg1,max1,avg2,max2
    __shared__ float s_hid [4][B][CR];
    __shared__ float s_a   [2][B][C];
    int tid = threadIdx.x;

    { // reduce stats partials
        int b = tid >> 6, c = tid & 63;
        float s0 = d_ps[tid][0] + d_ps[tid][1] + d_ps[tid][2] + d_ps[tid][3];
        float m0 = fmaxf(fmaxf(d_pm[tid][0], d_pm[tid][1]),
                         fmaxf(d_pm[tid][2], d_pm[tid][3]));
        int r1 = tid + 256;
        float s1 = d_ps[r1][0] + d_ps[r1][1] + d_ps[r1][2] + d_ps[r1][3];
        float m1 = fmaxf(fmaxf(d_pm[r1][0], d_pm[r1][1]),
                         fmaxf(d_pm[r1][2], d_pm[r1][3]));
        s_stat[0][b][c] = s0 * (1.f / HW);
        s_stat[1][b][c] = m0;
        s_stat[2][b][c] = s1 * (1.f / HW);
        s_stat[3][b][c] = m1;
    }
    __syncthreads();

    const float* Wp[4] = {w_a1, w_m1, w_a2, w_m2};
    const float* Bp[4] = {b_a1, b_m1, b_a2, b_m2};
    for (int e = tid; e < 4 * B * CR; e += 256) {
        int p = e >> 7, b = (e >> 5) & 3, k = e & 31;
        const float* wr = Wp[p] + k * C;
        float acc = Bp[p][k];
        #pragma unroll 8
        for (int c2 = 0; c2 < C; c2++) acc += s_stat[p][b][c2] * wr[c2];
        s_hid[p][b][k] = fmaxf(acc, 0.f);
    }
    __syncthreads();

    {
        int b = tid >> 6, i = tid & 63;
        float a1 = b_a11[i] + b_m11[i];
        float a2 = b_a22[i] + b_m22[i];
        #pragma unroll 8
        for (int k = 0; k < CR; k++) {
            a1 += s_hid[0][b][k] * w_a11[i * CR + k] + s_hid[1][b][k] * w_m11[i * CR + k];
            a2 += s_hid[2][b][k] * w_a22[i * CR + k] + s_hid[3][b][k] * w_m22[i * CR + k];
        }
        s_a[0][b][i] = a1;
        s_a[1][b][i] = a2;
    }
    __syncthreads();

    {
        int b = tid >> 6, i = tid & 63;
        for (int zz = 0; zz < 2; zz++) {
            float x = s_a[zz][b][i];
            const float* other = s_a[1 - zz][b];
            float m = -INFINITY;
            for (int j = 0; j < C; j++) m = fmaxf(m, x * other[j]);
            float* Srow = &d_S[zz][b][i * C];
            float Z = 0.f;
            for (int j = 0; j < C; j++) {
                float e2 = __expf(x * other[j] - m);
                Srow[j] = e2;
                Z += e2;
            }
            float inv = 1.f / Z;
            for (int j = 0; j < C; j++) {
                float v = Srow[j] * inv;
                Srow[j] = v;
                d_Sb[zz][b][i * C + j] = __float2bfloat16(v);
            }
        }
    }
    __syncthreads();

    {
        int b = tid >> 6, j = tid & 63;
        for (int zz = 0; zz < 2; zz++) {
            float s = 0.f;
            for (int i2 = 0; i2 < C; i2++) s += d_S[zz][b][i2 * C + j];
            d_wv[zz][b][j] = s * (1.f / C);
        }
    }
}

// ---------------- kernel 3: attention pooling via bf16 HMMA -----------------
#define PXT  256
#define FROW 264
#define SROW 72
#define ATP_SMEM_BYTES (64*FROW*2 + 64*SROW*2 + 64*4)

__global__ void __launch_bounds__(256, 2)
atpool_kernel(const float* __restrict__ f1, const float* __restrict__ f2) {
    extern __shared__ char smraw[];
    __nv_bfloat16* sF = (__nv_bfloat16*)smraw;
    __nv_bfloat16* sS = sF + 64 * FROW;
    float* sw = (float*)(sS + 64 * SROW);

    int tid = threadIdx.x, warp = tid >> 5, lane = tid & 31;
    int tile = blockIdx.x, b = blockIdx.y, z = blockIdx.z;  // z=0 (f1) first
    const float* f = (z ? f2 : f1) + (size_t)b * C * HW + tile * PXT;
    const __nv_bfloat16* Sg = d_Sb[z][b];

    for (int i = tid; i < C * C; i += 256)
        sS[(i >> 6) * SROW + (i & 63)] = Sg[i];
    if (tid < 64) sw[tid] = d_wv[z][b][tid];

    #pragma unroll
    for (int it = 0; it < 16; it++) {
        int lin = tid + it * 256;
        int c = lin >> 6, p4 = (lin & 63) * 4;
        float4 v = *(const float4*)(f + (size_t)c * HW + p4);
        uint32_t u0 = pack_bf16(v.x, v.y);
        uint32_t u1 = pack_bf16(v.z, v.w);
        *(uint2*)(sF + c * FROW + p4) = make_uint2(u0, u1);
    }
    __syncthreads();

    int pxw = warp * 32;
    float acc[4][4][4];
    #pragma unroll
    for (int mt = 0; mt < 4; mt++)
        #pragma unroll
        for (int nt = 0; nt < 4; nt++)
            #pragma unroll
            for (int r = 0; r < 4; r++) acc[mt][nt][r] = 0.f;

    #pragma unroll
    for (int kt = 0; kt < 4; kt++) {
        uint32_t a[4][4];
        #pragma unroll
        for (int mt = 0; mt < 4; mt++) {
            int row = mt * 16 + (lane & 15);
            int col = kt * 16 + ((lane & 16) ? 8 : 0);
            uint32_t ad = (uint32_t)__cvta_generic_to_shared(sS + row * SROW + col);
            ldsm_x4(a[mt], ad);
        }
        uint32_t bfr[2][4];
        #pragma unroll
        for (int h = 0; h < 2; h++) {
            int krow = kt * 16 + (lane & 15);
            int px   = pxw + h * 16 + ((lane & 16) ? 8 : 0);
            uint32_t ad = (uint32_t)__cvta_generic_to_shared(sF + krow * FROW + px);
            ldsm_x4_trans(bfr[h], ad);
        }
        #pragma unroll
        for (int mt = 0; mt < 4; mt++)
            #pragma unroll
            for (int nt = 0; nt < 4; nt++)
                mma_bf16(acc[mt][nt], a[mt],
                         bfr[nt >> 1][(nt & 1) * 2 + 0],
                         bfr[nt >> 1][(nt & 1) * 2 + 1]);
    }

    float* pmax = &d_pooled[z][b][1][tile * PXT];
    #pragma unroll
    for (int nt = 0; nt < 4; nt++) {
        float m0 = fmaxf(fmaxf(acc[0][nt][0], acc[0][nt][2]),
                         fmaxf(acc[1][nt][0], acc[1][nt][2]));
        m0 = fmaxf(m0, fmaxf(fmaxf(acc[2][nt][0], acc[2][nt][2]),
                             fmaxf(acc[3][nt][0], acc[3][nt][2])));
        float m1 = fmaxf(fmaxf(acc[0][nt][1], acc[0][nt][3]),
                         fmaxf(acc[1][nt][1], acc[1][nt][3]));
        m1 = fmaxf(m1, fmaxf(fmaxf(acc[2][nt][1], acc[2][nt][3]),
                             fmaxf(acc[3][nt][1], acc[3][nt][3])));
        #pragma unroll
        for (int off = 4; off < 32; off <<= 1) {
            m0 = fmaxf(m0, __shfl_xor_sync(0xffffffffu, m0, off));
            m1 = fmaxf(m1, __shfl_xor_sync(0xffffffffu, m1, off));
        }
        if (lane < 4) {
            int px = pxw + nt * 8 + lane * 2;
            pmax[px]     = m0;
            pmax[px + 1] = m1;
        }
    }

    float s = 0.f;
    const __nv_bfloat16* colp = sF + pxw + lane;
    #pragma unroll 16
    for (int k = 0; k < 64; k++)
        s += sw[k] * __bfloat162float(colp[k * FROW]);
    d_pooled[z][b][0][tile * PXT + pxw + lane] = s;
}

// ---------------- kernel 4: fused conv1(relu)+conv2, smem tiled --------------
// Output tile 64x16, halo 2; t1 never leaves smem.
#define CTX 64
#define CTY 16
__global__ void __launch_bounds__(256)
convf_kernel(const float* __restrict__ cw1, const float* __restrict__ cb1,
             const float* __restrict__ cw2, const float* __restrict__ cb2) {
    __shared__ float in0[20][68];
    __shared__ float in1[20][68];
    __shared__ float t1s[18][66];

    int tid = threadIdx.x;
    int ox = blockIdx.x * CTX;
    int oy = blockIdx.y * CTY;
    int zb = blockIdx.z; int z = zb >> 2, b = zb & 3;
    const float* p0 = d_pooled[z][b][0];
    const float* p1 = d_pooled[z][b][1];

    float w1r[18], w2r[9];
    #pragma unroll
    for (int i = 0; i < 18; i++) w1r[i] = cw1[i];
    #pragma unroll
    for (int i = 0; i < 9;  i++) w2r[i] = cw2[i];
    float bias1 = cb1[0], bias2 = cb2[0];

    for (int idx = tid; idx < 20 * 68; idx += 256) {
        int ly = idx / 68, lx = idx % 68;
        int gy = oy - 2 + ly, gx = ox - 2 + lx;
        bool ok = (gy >= 0) & (gy < 256) & (gx >= 0) & (gx < 256);
        int q = gy * 256 + gx;
        in0[ly][lx] = ok ? p0[q] : 0.f;
        in1[ly][lx] = ok ? p1[q] : 0.f;
    }
    __syncthreads();

    for (int idx = tid; idx < 18 * 66; idx += 256) {
        int ty = idx / 66, tx = idx % 66;
        int gy = oy - 1 + ty, gx = ox - 1 + tx;
        float v = 0.f;
        if ((gy >= 0) & (gy < 256) & (gx >= 0) & (gx < 256)) {
            float acc = bias1;
            #pragma unroll
            for (int dy = 0; dy < 3; dy++)
                #pragma unroll
                for (int dx = 0; dx < 3; dx++) {
                    acc += w1r[dy * 3 + dx]     * in0[ty + dy][tx + dx];
                    acc += w1r[9 + dy * 3 + dx] * in1[ty + dy][tx + dx];
                }
            v = fmaxf(acc, 0.f);
        }
        t1s[ty][tx] = v;
    }
    __syncthreads();

    #pragma unroll
    for (int r = 0; r < 4; r++) {
        int idx = tid + r * 256;
        int y = idx >> 6, x = idx & 63;
        float acc = bias2;
        #pragma unroll
        for (int dy = 0; dy < 3; dy++)
            #pragma unroll
            for (int dx = 0; dx < 3; dx++)
                acc += w2r[dy * 3 + dx] * t1s[y + dy][x + dx];
        d_t2[z][b][(oy + y) * 256 + (ox + x)] = acc;
    }
}

// ---------------- kernel 5: softmax stats over HW per (z,b) -----------------
__global__ void softstat_kernel() {
    __shared__ float sred[1024];
    int tid = threadIdx.x;
    int z = blockIdx.x >> 2, b = blockIdx.x & 3;
    const float* yv = d_t2[z][b];
    float m = -INFINITY;
    for (int i = tid; i < HW; i += 1024) m = fmaxf(m, yv[i]);
    sred[tid] = m;
    __syncthreads();
    for (int o = 512; o > 0; o >>= 1) {
        if (tid < o) sred[tid] = fmaxf(sred[tid], sred[tid + o]);
        __syncthreads();
    }
    float M = sred[0];
    __syncthreads();
    float s = 0.f;
    for (int i = tid; i < HW; i += 1024) s += __expf(yv[i] - M);
    sred[tid] = s;
    __syncthreads();
    for (int o = 512; o > 0; o >>= 1) {
        if (tid < o) sred[tid] += sred[tid + o];
        __syncthreads();
    }
    if (tid == 0) { d_smax[z][b] = M; d_ssum[z][b] = sred[0]; }
}

// ---------------- kernel 6: materialize gate --------------------------------
__global__ void gate_kernel() {
    int zb = blockIdx.y; int z = zb >> 2, b = zb & 3;
    int i4 = blockIdx.x * 256 + threadIdx.x;
    float M    = d_smax[z][b];
    float rinv = 1.f / d_ssum[z][b];
    float4 yv = *(const float4*)(&d_t2[z][b][i4 * 4]);
    float4 g;
    g.x = __expf(yv.x - M) * rinv;
    g.y = __expf(yv.y - M) * rinv;
    g.z = __expf(yv.z - M) * rinv;
    g.w = __expf(yv.w - M) * rinv;
    *(float4*)(&d_g[z][b][i4 * 4]) = g;
}

// ---------------- kernel 7: o = f*(1+g), f2 first (L2 reuse from atpool) ----
__global__ void out_kernel(const float* __restrict__ f1,
                           const float* __restrict__ f2,
                           float* __restrict__ out) {
    unsigned idx  = blockIdx.x * 256u + threadIdx.x;
    unsigned pix4 = idx & 16383u;
    unsigned c    = (idx >> 14) & 63u;
    unsigned b    = (idx >> 20) & 3u;
    unsigned z    = 1u - (idx >> 22);      // f2 first
    const float* f = z ? f2 : f1;
    float4 g = *(const float4*)(&d_g[z][b][pix4 * 4]);
    size_t base = ((size_t)(b * 64u + c)) * HW + pix4 * 4u;
    float4 v = *(const float4*)(f + base);
    float4 o;
    o.x = fmaf(v.x, g.x, v.x);
    o.y = fmaf(v.y, g.y, v.y);
    o.z = fmaf(v.z, g.z, v.z);
    o.w = fmaf(v.w, g.w, v.w);
    *(float4*)(out + (size_t)z * ((size_t)B * C * HW) + base) = o;
}

// ---------------- launch ------------------------------------------------------
extern "C" void kernel_launch(void* const* d_in, const int* in_sizes, int n_in,
                              void* d_out, int out_size) {
    const float* f1 = (const float*)d_in[0];
    const float* f2 = (const float*)d_in[1];

    cudaFuncSetAttribute(atpool_kernel,
                         cudaFuncAttributeMaxDynamicSharedMemorySize,
                         ATP_SMEM_BYTES);

    stats_kernel<<<2048, 256>>>(f1, f2);

    mlp_kernel<<<1, 256>>>(
        (const float*)d_in[2],  (const float*)d_in[3],
        (const float*)d_in[4],  (const float*)d_in[5],
        (const float*)d_in[6],  (const float*)d_in[7],
        (const float*)d_in[8],  (const float*)d_in[9],
        (const float*)d_in[10], (const float*)d_in[11],
        (const float*)d_in[12], (const float*)d_in[13],
        (const float*)d_in[14], (const float*)d_in[15],
        (const float*)d_in[16], (const float*)d_in[17]);

    atpool_kernel<<<dim3(256, 4, 2), 256, ATP_SMEM_BYTES>>>(f1, f2);

    convf_kernel<<<dim3(4, 16, 8), 256>>>(
        (const float*)d_in[18], (const float*)d_in[19],
        (const float*)d_in[20], (const float*)d_in[21]);

    softstat_kernel<<<8, 1024>>>();

    gate_kernel<<<dim3(64, 8), 256>>>();

    out_kernel<<<32768, 256>>>(f1, f2, (float*)d_out);
}

// round 5
// speedup vs baseline: 1.3999x; 1.2269x over previous
#include <cuda_runtime.h>
#include <cuda_bf16.h>
#include <math.h>
#include <stdint.h>

#define B  4
#define C  64
#define CR 32
#define HW 65536

// ---------------- scratch (device globals) ----------------------------------
__device__ float d_ps[512][4];                // stats partial sums
__device__ float d_pm[512][4];                // stats partial maxes
__device__ float d_S  [2][B][C*C];
__device__ __nv_bfloat16 d_Sb[2][B][C*C];
__device__ float d_wv [2][B][C];
__device__ float d_pooled[2][B][2][HW];
__device__ float d_t2[2][B][HW];
__device__ float d_g [2][B][HW];
__device__ float d_cmax[8][64];               // conv softmax partial max
__device__ float d_csum[8][64];               // conv softmax partial sumexp

// ---------------- PTX helpers ------------------------------------------------
__device__ __forceinline__ uint32_t pack_bf16(float lo, float hi) {
    uint32_t d;
    asm("cvt.rn.bf16x2.f32 %0, %1, %2;" : "=r"(d) : "f"(hi), "f"(lo));
    return d;
}
__device__ __forceinline__ void ldsm_x4(uint32_t r[4], uint32_t addr) {
    asm volatile("ldmatrix.sync.aligned.m8n8.x4.shared.b16 {%0,%1,%2,%3}, [%4];"
                 : "=r"(r[0]), "=r"(r[1]), "=r"(r[2]), "=r"(r[3]) : "r"(addr));
}
__device__ __forceinline__ void ldsm_x4_trans(uint32_t r[4], uint32_t addr) {
    asm volatile("ldmatrix.sync.aligned.m8n8.x4.trans.shared.b16 {%0,%1,%2,%3}, [%4];"
                 : "=r"(r[0]), "=r"(r[1]), "=r"(r[2]), "=r"(r[3]) : "r"(addr));
}
__device__ __forceinline__ void mma_bf16(float d[4], const uint32_t a[4],
                                         uint32_t b0, uint32_t b1) {
    asm volatile(
        "mma.sync.aligned.m16n8k16.row.col.f32.bf16.bf16.f32 "
        "{%0,%1,%2,%3}, {%4,%5,%6,%7}, {%8,%9}, {%0,%1,%2,%3};"
        : "+f"(d[0]), "+f"(d[1]), "+f"(d[2]), "+f"(d[3])
        : "r"(a[0]), "r"(a[1]), "r"(a[2]), "r"(a[3]), "r"(b0), "r"(b1));
}

// ---------------- kernel 1: stats partials ----------------------------------
__global__ void stats_kernel(const float* __restrict__ f1,
                             const float* __restrict__ f2) {
    int lin   = blockIdx.x;              // 0..2047
    int row   = 511 - (lin >> 2);        // f2 chunks first
    int chunk = lin & 3;
    const float* f = (row < 256) ? (f1 + (size_t)row * HW)
                                 : (f2 + (size_t)(row - 256) * HW);
    int tid = threadIdx.x;
    const float4* f4 = (const float4*)f + chunk * 4096;

    float s = 0.f, m = -INFINITY;
    #pragma unroll
    for (int k = 0; k < 16; k++) {
        float4 v = f4[tid + k * 256];
        s += (v.x + v.y) + (v.z + v.w);
        m = fmaxf(m, fmaxf(fmaxf(v.x, v.y), fmaxf(v.z, v.w)));
    }
    __shared__ float ss[256], sm[256];
    ss[tid] = s; sm[tid] = m;
    __syncthreads();
    for (int o = 128; o > 0; o >>= 1) {
        if (tid < o) { ss[tid] += ss[tid + o]; sm[tid] = fmaxf(sm[tid], sm[tid + o]); }
        __syncthreads();
    }
    if (tid == 0) { d_ps[row][chunk] = ss[0]; d_pm[row][chunk] = sm[0]; }
}

// ---------------- kernel 2: reduce partials + MLPs + rank-1 cross softmax ---
__global__ void mlp_kernel(
    const float* __restrict__ w_a1,  const float* __restrict__ b_a1,
    const float* __restrict__ w_m1,  const float* __restrict__ b_m1,
    const float* __restrict__ w_a11, const float* __restrict__ b_a11,
    const float* __restrict__ w_m11, const float* __restrict__ b_m11,
    const float* __restrict__ w_a2,  const float* __restrict__ b_a2,
    const float* __restrict__ w_m2,  const float* __restrict__ b_m2,
    const float* __restrict__ w_a22, const float* __restrict__ b_a22,
    const float* __restrict__ w_m22, const float* __restrict__ b_m22)
{
    __shared__ float s_stat[4][B][C];
    __shared__ float s_hid [4][B][CR];
    __shared__ float s_a   [2][B][C];
    int tid = threadIdx.x;

    {
        int b = tid >> 6, c = tid & 63;
        float s0 = d_ps[tid][0] + d_ps[tid][1] + d_ps[tid][2] + d_ps[tid][3];
        float m0 = fmaxf(fmaxf(d_pm[tid][0], d_pm[tid][1]),
                         fmaxf(d_pm[tid][2], d_pm[tid][3]));
        int r1 = tid + 256;
        float s1 = d_ps[r1][0] + d_ps[r1][1] + d_ps[r1][2] + d_ps[r1][3];
        float m1 = fmaxf(fmaxf(d_pm[r1][0], d_pm[r1][1]),
                         fmaxf(d_pm[r1][2], d_pm[r1][3]));
        s_stat[0][b][c] = s0 * (1.f / HW);
        s_stat[1][b][c] = m0;
        s_stat[2][b][c] = s1 * (1.f / HW);
        s_stat[3][b][c] = m1;
    }
    __syncthreads();

    const float* Wp[4] = {w_a1, w_m1, w_a2, w_m2};
    const float* Bp[4] = {b_a1, b_m1, b_a2, b_m2};
    for (int e = tid; e < 4 * B * CR; e += 256) {
        int p = e >> 7, b = (e >> 5) & 3, k = e & 31;
        const float* wr = Wp[p] + k * C;
        float acc = Bp[p][k];
        #pragma unroll 8
        for (int c2 = 0; c2 < C; c2++) acc += s_stat[p][b][c2] * wr[c2];
        s_hid[p][b][k] = fmaxf(acc, 0.f);
    }
    __syncthreads();

    {
        int b = tid >> 6, i = tid & 63;
        float a1 = b_a11[i] + b_m11[i];
        float a2 = b_a22[i] + b_m22[i];
        #pragma unroll 8
        for (int k = 0; k < CR; k++) {
            a1 += s_hid[0][b][k] * w_a11[i * CR + k] + s_hid[1][b][k] * w_m11[i * CR + k];
            a2 += s_hid[2][b][k] * w_a22[i * CR + k] + s_hid[3][b][k] * w_m22[i * CR + k];
        }
        s_a[0][b][i] = a1;
        s_a[1][b][i] = a2;
    }
    __syncthreads();

    {
        int b = tid >> 6, i = tid & 63;
        for (int zz = 0; zz < 2; zz++) {
            float x = s_a[zz][b][i];
            const float* other = s_a[1 - zz][b];
            float m = -INFINITY;
            for (int j = 0; j < C; j++) m = fmaxf(m, x * other[j]);
            float* Srow = &d_S[zz][b][i * C];
            float Z = 0.f;
            for (int j = 0; j < C; j++) {
                float e2 = __expf(x * other[j] - m);
                Srow[j] = e2;
                Z += e2;
            }
            float inv = 1.f / Z;
            for (int j = 0; j < C; j++) Srow[j] *= inv;
        }
    }
}

// ---------------- kernel 3: S -> bf16, column means (positions atpool 4th) ---
__global__ void sprep_kernel() {
    int zb = blockIdx.x; int zz = zb >> 2, b = zb & 3;
    int tid = threadIdx.x;
    const float* S = d_S[zz][b];
    for (int i = tid; i < C * C; i += 256)
        d_Sb[zz][b][i] = __float2bfloat16(S[i]);
    if (tid < 64) {
        float s = 0.f;
        #pragma unroll 8
        for (int i = 0; i < C; i++) s += S[i * C + tid];
        d_wv[zz][b][tid] = s * (1.f / C);
    }
}

// ---------------- kernel 4: attention pooling via bf16 HMMA (PROFILED) ------
#define PXT  256
#define FROW 264
#define SROW 72
#define ATP_SMEM_BYTES (64*FROW*2 + 64*SROW*2 + 64*4)

__global__ void __launch_bounds__(256, 2)
atpool_kernel(const float* __restrict__ f1, const float* __restrict__ f2) {
    extern __shared__ char smraw[];
    __nv_bfloat16* sF = (__nv_bfloat16*)smraw;
    __nv_bfloat16* sS = sF + 64 * FROW;
    float* sw = (float*)(sS + 64 * SROW);

    int tid = threadIdx.x, warp = tid >> 5, lane = tid & 31;
    int tile = blockIdx.x, b = blockIdx.y, z = blockIdx.z;
    const float* f = (z ? f2 : f1) + (size_t)b * C * HW + tile * PXT;
    const __nv_bfloat16* Sg = d_Sb[z][b];

    for (int i = tid; i < C * C; i += 256)
        sS[(i >> 6) * SROW + (i & 63)] = Sg[i];
    if (tid < 64) sw[tid] = d_wv[z][b][tid];

    #pragma unroll
    for (int it = 0; it < 16; it++) {
        int lin = tid + it * 256;
        int c = lin >> 6, p4 = (lin & 63) * 4;
        float4 v = *(const float4*)(f + (size_t)c * HW + p4);
        uint32_t u0 = pack_bf16(v.x, v.y);
        uint32_t u1 = pack_bf16(v.z, v.w);
        *(uint2*)(sF + c * FROW + p4) = make_uint2(u0, u1);
    }
    __syncthreads();

    int pxw = warp * 32;
    float acc[4][4][4];
    #pragma unroll
    for (int mt = 0; mt < 4; mt++)
        #pragma unroll
        for (int nt = 0; nt < 4; nt++)
            #pragma unroll
            for (int r = 0; r < 4; r++) acc[mt][nt][r] = 0.f;

    #pragma unroll
    for (int kt = 0; kt < 4; kt++) {
        uint32_t a[4][4];
        #pragma unroll
        for (int mt = 0; mt < 4; mt++) {
            int row = mt * 16 + (lane & 15);
            int col = kt * 16 + ((lane & 16) ? 8 : 0);
            uint32_t ad = (uint32_t)__cvta_generic_to_shared(sS + row * SROW + col);
            ldsm_x4(a[mt], ad);
        }
        uint32_t bfr[2][4];
        #pragma unroll
        for (int h = 0; h < 2; h++) {
            int krow = kt * 16 + (lane & 15);
            int px   = pxw + h * 16 + ((lane & 16) ? 8 : 0);
            uint32_t ad = (uint32_t)__cvta_generic_to_shared(sF + krow * FROW + px);
            ldsm_x4_trans(bfr[h], ad);
        }
        #pragma unroll
        for (int mt = 0; mt < 4; mt++)
            #pragma unroll
            for (int nt = 0; nt < 4; nt++)
                mma_bf16(acc[mt][nt], a[mt],
                         bfr[nt >> 1][(nt & 1) * 2 + 0],
                         bfr[nt >> 1][(nt & 1) * 2 + 1]);
    }

    float* pmax = &d_pooled[z][b][1][tile * PXT];
    #pragma unroll
    for (int nt = 0; nt < 4; nt++) {
        float m0 = fmaxf(fmaxf(acc[0][nt][0], acc[0][nt][2]),
                         fmaxf(acc[1][nt][0], acc[1][nt][2]));
        m0 = fmaxf(m0, fmaxf(fmaxf(acc[2][nt][0], acc[2][nt][2]),
                             fmaxf(acc[3][nt][0], acc[3][nt][2])));
        float m1 = fmaxf(fmaxf(acc[0][nt][1], acc[0][nt][3]),
                         fmaxf(acc[1][nt][1], acc[1][nt][3]));
        m1 = fmaxf(m1, fmaxf(fmaxf(acc[2][nt][1], acc[2][nt][3]),
                             fmaxf(acc[3][nt][1], acc[3][nt][3])));
        #pragma unroll
        for (int off = 4; off < 32; off <<= 1) {
            m0 = fmaxf(m0, __shfl_xor_sync(0xffffffffu, m0, off));
            m1 = fmaxf(m1, __shfl_xor_sync(0xffffffffu, m1, off));
        }
        if (lane < 4) {
            int px = pxw + nt * 8 + lane * 2;
            pmax[px]     = m0;
            pmax[px + 1] = m1;
        }
    }

    float s = 0.f;
    const __nv_bfloat16* colp = sF + pxw + lane;
    #pragma unroll 16
    for (int k = 0; k < 64; k++)
        s += sw[k] * __bfloat162float(colp[k * FROW]);
    d_pooled[z][b][0][tile * PXT + pxw + lane] = s;
}

// ---------------- kernel 5: fused conv1+conv2 + softmax partials ------------
#define CTX 64
#define CTY 16
__global__ void __launch_bounds__(256)
convf_kernel(const float* __restrict__ cw1, const float* __restrict__ cb1,
             const float* __restrict__ cw2, const float* __restrict__ cb2) {
    __shared__ float in0[20][68];
    __shared__ float in1[20][68];
    __shared__ float t1s[18][66];
    __shared__ float rbuf[256];

    int tid = threadIdx.x;
    int ox = blockIdx.x * CTX;
    int oy = blockIdx.y * CTY;
    int zb = blockIdx.z; int z = zb >> 2, b = zb & 3;
    const float* p0 = d_pooled[z][b][0];
    const float* p1 = d_pooled[z][b][1];

    float w1r[18], w2r[9];
    #pragma unroll
    for (int i = 0; i < 18; i++) w1r[i] = cw1[i];
    #pragma unroll
    for (int i = 0; i < 9;  i++) w2r[i] = cw2[i];
    float bias1 = cb1[0], bias2 = cb2[0];

    for (int idx = tid; idx < 20 * 68; idx += 256) {
        int ly = idx / 68, lx = idx % 68;
        int gy = oy - 2 + ly, gx = ox - 2 + lx;
        bool ok = (gy >= 0) & (gy < 256) & (gx >= 0) & (gx < 256);
        int q = gy * 256 + gx;
        in0[ly][lx] = ok ? p0[q] : 0.f;
        in1[ly][lx] = ok ? p1[q] : 0.f;
    }
    __syncthreads();

    for (int idx = tid; idx < 18 * 66; idx += 256) {
        int ty = idx / 66, tx = idx % 66;
        int gy = oy - 1 + ty, gx = ox - 1 + tx;
        float v = 0.f;
        if ((gy >= 0) & (gy < 256) & (gx >= 0) & (gx < 256)) {
            float acc = bias1;
            #pragma unroll
            for (int dy = 0; dy < 3; dy++)
                #pragma unroll
                for (int dx = 0; dx < 3; dx++) {
                    acc += w1r[dy * 3 + dx]     * in0[ty + dy][tx + dx];
                    acc += w1r[9 + dy * 3 + dx] * in1[ty + dy][tx + dx];
                }
            v = fmaxf(acc, 0.f);
        }
        t1s[ty][tx] = v;
    }
    __syncthreads();

    float vals[4];
    #pragma unroll
    for (int r = 0; r < 4; r++) {
        int idx = tid + r * 256;
        int y = idx >> 6, x = idx & 63;
        float acc = bias2;
        #pragma unroll
        for (int dy = 0; dy < 3; dy++)
            #pragma unroll
            for (int dx = 0; dx < 3; dx++)
                acc += w2r[dy * 3 + dx] * t1s[y + dy][x + dx];
        vals[r] = acc;
        d_t2[z][b][(oy + y) * 256 + (ox + x)] = acc;
    }

    // online softmax partials for this block's 1024 outputs
    float lm = fmaxf(fmaxf(vals[0], vals[1]), fmaxf(vals[2], vals[3]));
    rbuf[tid] = lm;
    __syncthreads();
    for (int o = 128; o > 0; o >>= 1) {
        if (tid < o) rbuf[tid] = fmaxf(rbuf[tid], rbuf[tid + o]);
        __syncthreads();
    }
    float Mblk = rbuf[0];
    __syncthreads();
    float ls = __expf(vals[0] - Mblk) + __expf(vals[1] - Mblk)
             + __expf(vals[2] - Mblk) + __expf(vals[3] - Mblk);
    rbuf[tid] = ls;
    __syncthreads();
    for (int o = 128; o > 0; o >>= 1) {
        if (tid < o) rbuf[tid] += rbuf[tid + o];
        __syncthreads();
    }
    if (tid == 0) {
        int blk = blockIdx.y * 4 + blockIdx.x;   // 0..63
        d_cmax[zb][blk] = Mblk;
        d_csum[zb][blk] = rbuf[0];
    }
}

// ---------------- kernel 6: gate = softmax(t2) over HW ----------------------
__global__ void gate_kernel() {
    __shared__ float sM, sS;
    int tid = threadIdx.x;
    int zb = blockIdx.y; int z = zb >> 2, b = zb & 3;

    if (tid < 32) {
        float m0 = d_cmax[zb][tid], m1 = d_cmax[zb][tid + 32];
        float mm = fmaxf(m0, m1);
        #pragma unroll
        for (int off = 16; off > 0; off >>= 1)
            mm = fmaxf(mm, __shfl_xor_sync(0xffffffffu, mm, off));
        float s = d_csum[zb][tid]      * __expf(m0 - mm)
                + d_csum[zb][tid + 32] * __expf(m1 - mm);
        #pragma unroll
        for (int off = 16; off > 0; off >>= 1)
            s += __shfl_xor_sync(0xffffffffu, s, off);
        if (tid == 0) { sM = mm; sS = s; }
    }
    __syncthreads();
    float M = sM, rinv = 1.f / sS;

    int i4 = blockIdx.x * 256 + tid;
    float4 yv = *(const float4*)(&d_t2[z][b][i4 * 4]);
    float4 g;
    g.x = __expf(yv.x - M) * rinv;
    g.y = __expf(yv.y - M) * rinv;
    g.z = __expf(yv.z - M) * rinv;
    g.w = __expf(yv.w - M) * rinv;
    *(float4*)(&d_g[z][b][i4 * 4]) = g;
}

// ---------------- kernel 7: o = f*(1+g), 2 float4 per thread ----------------
__global__ void out_kernel(const float* __restrict__ f1,
                           const float* __restrict__ f2,
                           float* __restrict__ out) {
    unsigned idx  = blockIdx.x * 256u + threadIdx.x;   // pair index
    unsigned pr   = idx & 8191u;                       // float4-pair in (z,b,c)
    unsigned c    = (idx >> 13) & 63u;
    unsigned b    = (idx >> 19) & 3u;
    unsigned z    = 1u - (idx >> 21);                  // f2 first
    const float* f = z ? f2 : f1;

    const float4* gp = (const float4*)&d_g[z][b][pr * 8];
    float4 g0 = gp[0], g1 = gp[1];
    size_t base = ((size_t)(b * 64u + c)) * HW + pr * 8u;
    const float4* fp = (const float4*)(f + base);
    float4 v0 = fp[0], v1 = fp[1];
    float4 o0, o1;
    o0.x = fmaf(v0.x, g0.x, v0.x); o0.y = fmaf(v0.y, g0.y, v0.y);
    o0.z = fmaf(v0.z, g0.z, v0.z); o0.w = fmaf(v0.w, g0.w, v0.w);
    o1.x = fmaf(v1.x, g1.x, v1.x); o1.y = fmaf(v1.y, g1.y, v1.y);
    o1.z = fmaf(v1.z, g1.z, v1.z); o1.w = fmaf(v1.w, g1.w, v1.w);
    float4* op = (float4*)(out + (size_t)z * ((size_t)B * C * HW) + base);
    op[0] = o0; op[1] = o1;
}

// ---------------- launch ------------------------------------------------------
extern "C" void kernel_launch(void* const* d_in, const int* in_sizes, int n_in,
                              void* d_out, int out_size) {
    const float* f1 = (const float*)d_in[0];
    const float* f2 = (const float*)d_in[1];

    cudaFuncSetAttribute(atpool_kernel,
                         cudaFuncAttributeMaxDynamicSharedMemorySize,
                         ATP_SMEM_BYTES);

    stats_kernel<<<2048, 256>>>(f1, f2);

    mlp_kernel<<<1, 256>>>(
        (const float*)d_in[2],  (const float*)d_in[3],
        (const float*)d_in[4],  (const float*)d_in[5],
        (const float*)d_in[6],  (const float*)d_in[7],
        (const float*)d_in[8],  (const float*)d_in[9],
        (const float*)d_in[10], (const float*)d_in[11],
        (const float*)d_in[12], (const float*)d_in[13],
        (const float*)d_in[14], (const float*)d_in[15],
        (const float*)d_in[16], (const float*)d_in[17]);

    sprep_kernel<<<8, 256>>>();

    atpool_kernel<<<dim3(256, 4, 2), 256, ATP_SMEM_BYTES>>>(f1, f2);

    convf_kernel<<<dim3(4, 16, 8), 256>>>(
        (const float*)d_in[18], (const float*)d_in[19],
        (const float*)d_in[20], (const float*)d_in[21]);

    gate_kernel<<<dim3(64, 8), 256>>>();

    out_kernel<<<16384, 256>>>(f1, f2, (float*)d_out);
}

// round 6
// speedup vs baseline: 1.5023x; 1.0732x over previous
#include <cuda_runtime.h>
#include <cuda_bf16.h>
#include <math.h>
#include <stdint.h>

#define B  4
#define C  64
#define CR 32
#define HW 65536

// ---------------- scratch (device globals) ----------------------------------
__device__ float d_ps[512][4];                // stats partial sums
__device__ float d_pm[512][4];                // stats partial maxes
__device__ float d_S  [2][B][C*C];
__device__ __nv_bfloat16 d_Sb[2][B][C*C];
__device__ float d_wv [2][B][C];
__device__ float d_pooled[2][B][2][HW];
__device__ float d_t2[2][B][HW];
__device__ float d_g [2][B][HW];
__device__ float d_cmax[8][64];               // conv softmax partial max
__device__ float d_csum[8][64];               // conv softmax partial sumexp

// ---------------- PTX helpers ------------------------------------------------
__device__ __forceinline__ uint32_t pack_bf16(float lo, float hi) {
    uint32_t d;
    asm("cvt.rn.bf16x2.f32 %0, %1, %2;" : "=r"(d) : "f"(hi), "f"(lo));
    return d;
}
__device__ __forceinline__ void ldsm_x4(uint32_t r[4], uint32_t addr) {
    asm volatile("ldmatrix.sync.aligned.m8n8.x4.shared.b16 {%0,%1,%2,%3}, [%4];"
                 : "=r"(r[0]), "=r"(r[1]), "=r"(r[2]), "=r"(r[3]) : "r"(addr));
}
__device__ __forceinline__ void ldsm_x4_trans(uint32_t r[4], uint32_t addr) {
    asm volatile("ldmatrix.sync.aligned.m8n8.x4.trans.shared.b16 {%0,%1,%2,%3}, [%4];"
                 : "=r"(r[0]), "=r"(r[1]), "=r"(r[2]), "=r"(r[3]) : "r"(addr));
}
__device__ __forceinline__ void mma_bf16(float d[4], const uint32_t a[4],
                                         uint32_t b0, uint32_t b1) {
    asm volatile(
        "mma.sync.aligned.m16n8k16.row.col.f32.bf16.bf16.f32 "
        "{%0,%1,%2,%3}, {%4,%5,%6,%7}, {%8,%9}, {%0,%1,%2,%3};"
        : "+f"(d[0]), "+f"(d[1]), "+f"(d[2]), "+f"(d[3])
        : "r"(a[0]), "r"(a[1]), "r"(a[2]), "r"(a[3]), "r"(b0), "r"(b1));
}

// ---------------- kernel 1: stats partials ----------------------------------
__global__ void stats_kernel(const float* __restrict__ f1,
                             const float* __restrict__ f2) {
    int lin   = blockIdx.x;              // 0..2047
    int row   = 511 - (lin >> 2);        // f2 chunks first
    int chunk = lin & 3;
    const float* f = (row < 256) ? (f1 + (size_t)row * HW)
                                 : (f2 + (size_t)(row - 256) * HW);
    int tid = threadIdx.x;
    const float4* f4 = (const float4*)f + chunk * 4096;

    float s = 0.f, m = -INFINITY;
    #pragma unroll
    for (int k = 0; k < 16; k++) {
        float4 v = f4[tid + k * 256];
        s += (v.x + v.y) + (v.z + v.w);
        m = fmaxf(m, fmaxf(fmaxf(v.x, v.y), fmaxf(v.z, v.w)));
    }
    __shared__ float ss[256], sm[256];
    ss[tid] = s; sm[tid] = m;
    __syncthreads();
    for (int o = 128; o > 0; o >>= 1) {
        if (tid < o) { ss[tid] += ss[tid + o]; sm[tid] = fmaxf(sm[tid], sm[tid + o]); }
        __syncthreads();
    }
    if (tid == 0) { d_ps[row][chunk] = ss[0]; d_pm[row][chunk] = sm[0]; }
}

// ---------------- kernel 2: reduce partials + MLPs + rank-1 cross softmax ---
__global__ void mlp_kernel(
    const float* __restrict__ w_a1,  const float* __restrict__ b_a1,
    const float* __restrict__ w_m1,  const float* __restrict__ b_m1,
    const float* __restrict__ w_a11, const float* __restrict__ b_a11,
    const float* __restrict__ w_m11, const float* __restrict__ b_m11,
    const float* __restrict__ w_a2,  const float* __restrict__ b_a2,
    const float* __restrict__ w_m2,  const float* __restrict__ b_m2,
    const float* __restrict__ w_a22, const float* __restrict__ b_a22,
    const float* __restrict__ w_m22, const float* __restrict__ b_m22)
{
    __shared__ float s_stat[4][B][C];
    __shared__ float s_hid [4][B][CR];
    __shared__ float s_a   [2][B][C];
    int tid = threadIdx.x;

    {
        int b = tid >> 6, c = tid & 63;
        float s0 = d_ps[tid][0] + d_ps[tid][1] + d_ps[tid][2] + d_ps[tid][3];
        float m0 = fmaxf(fmaxf(d_pm[tid][0], d_pm[tid][1]),
                         fmaxf(d_pm[tid][2], d_pm[tid][3]));
        int r1 = tid + 256;
        float s1 = d_ps[r1][0] + d_ps[r1][1] + d_ps[r1][2] + d_ps[r1][3];
        float m1 = fmaxf(fmaxf(d_pm[r1][0], d_pm[r1][1]),
                         fmaxf(d_pm[r1][2], d_pm[r1][3]));
        s_stat[0][b][c] = s0 * (1.f / HW);
        s_stat[1][b][c] = m0;
        s_stat[2][b][c] = s1 * (1.f / HW);
        s_stat[3][b][c] = m1;
    }
    __syncthreads();

    const float* Wp[4] = {w_a1, w_m1, w_a2, w_m2};
    const float* Bp[4] = {b_a1, b_m1, b_a2, b_m2};
    for (int e = tid; e < 4 * B * CR; e += 256) {
        int p = e >> 7, b = (e >> 5) & 3, k = e & 31;
        const float* wr = Wp[p] + k * C;
        float acc = Bp[p][k];
        #pragma unroll 8
        for (int c2 = 0; c2 < C; c2++) acc += s_stat[p][b][c2] * wr[c2];
        s_hid[p][b][k] = fmaxf(acc, 0.f);
    }
    __syncthreads();

    {
        int b = tid >> 6, i = tid & 63;
        float a1 = b_a11[i] + b_m11[i];
        float a2 = b_a22[i] + b_m22[i];
        #pragma unroll 8
        for (int k = 0; k < CR; k++) {
            a1 += s_hid[0][b][k] * w_a11[i * CR + k] + s_hid[1][b][k] * w_m11[i * CR + k];
            a2 += s_hid[2][b][k] * w_a22[i * CR + k] + s_hid[3][b][k] * w_m22[i * CR + k];
        }
        s_a[0][b][i] = a1;
        s_a[1][b][i] = a2;
    }
    __syncthreads();

    {
        int b = tid >> 6, i = tid & 63;
        for (int zz = 0; zz < 2; zz++) {
            float x = s_a[zz][b][i];
            const float* other = s_a[1 - zz][b];
            float m = -INFINITY;
            for (int j = 0; j < C; j++) m = fmaxf(m, x * other[j]);
            float* Srow = &d_S[zz][b][i * C];
            float Z = 0.f;
            for (int j = 0; j < C; j++) {
                float e2 = __expf(x * other[j] - m);
                Srow[j] = e2;
                Z += e2;
            }
            float inv = 1.f / Z;
            for (int j = 0; j < C; j++) Srow[j] *= inv;
        }
    }
}

// ---------------- kernel 3: S -> bf16, column means --------------------------
__global__ void sprep_kernel() {
    int zb = blockIdx.x; int zz = zb >> 2, b = zb & 3;
    int tid = threadIdx.x;
    const float* S = d_S[zz][b];
    for (int i = tid; i < C * C; i += 256)
        d_Sb[zz][b][i] = __float2bfloat16(S[i]);
    if (tid < 64) {
        float s = 0.f;
        #pragma unroll 8
        for (int i = 0; i < C; i++) s += S[i * C + tid];
        d_wv[zz][b][tid] = s * (1.f / C);
    }
}

// ---------------- kernel 4: attention pooling, i-chunked HMMA ---------------
// i processed in 4 chunks of 16 -> acc only 16 regs, runmax 8; 4 CTAs/SM.
#define PXT  256
#define FROW 264
#define SROW 72
#define ATP_SMEM_BYTES (64*FROW*2 + 64*SROW*2 + 64*4)

__global__ void __launch_bounds__(256, 4)
atpool_kernel(const float* __restrict__ f1, const float* __restrict__ f2) {
    extern __shared__ char smraw[];
    __nv_bfloat16* sF = (__nv_bfloat16*)smraw;        // [64][FROW]
    __nv_bfloat16* sS = sF + 64 * FROW;               // [64][SROW]
    float* sw = (float*)(sS + 64 * SROW);             // [64]

    int tid = threadIdx.x, warp = tid >> 5, lane = tid & 31;
    int tile = blockIdx.x, b = blockIdx.y, z = blockIdx.z;
    const float* f = (z ? f2 : f1) + (size_t)b * C * HW + tile * PXT;
    const __nv_bfloat16* Sg = d_Sb[z][b];

    for (int i = tid; i < C * C; i += 256)
        sS[(i >> 6) * SROW + (i & 63)] = Sg[i];
    if (tid < 64) sw[tid] = d_wv[z][b][tid];

    #pragma unroll 8
    for (int it = 0; it < 16; it++) {
        int lin = tid + it * 256;
        int c = lin >> 6, p4 = (lin & 63) * 4;
        float4 v = *(const float4*)(f + (size_t)c * HW + p4);
        uint32_t u0 = pack_bf16(v.x, v.y);
        uint32_t u1 = pack_bf16(v.z, v.w);
        *(uint2*)(sF + c * FROW + p4) = make_uint2(u0, u1);
    }
    __syncthreads();

    int pxw = warp * 32;
    float rm0[4], rm1[4];                     // running max per n8 tile
    #pragma unroll
    for (int nt = 0; nt < 4; nt++) { rm0[nt] = -INFINITY; rm1[nt] = -INFINITY; }

    #pragma unroll
    for (int mt = 0; mt < 4; mt++) {          // i chunk: 16 channels
        float acc[4][4];
        #pragma unroll
        for (int nt = 0; nt < 4; nt++)
            #pragma unroll
            for (int r = 0; r < 4; r++) acc[nt][r] = 0.f;

        #pragma unroll
        for (int kt = 0; kt < 4; kt++) {
            uint32_t a[4];
            {
                int row = mt * 16 + (lane & 15);
                int col = kt * 16 + ((lane & 16) ? 8 : 0);
                uint32_t ad = (uint32_t)__cvta_generic_to_shared(sS + row * SROW + col);
                ldsm_x4(a, ad);
            }
            uint32_t bfr[2][4];
            #pragma unroll
            for (int h = 0; h < 2; h++) {
                int krow = kt * 16 + (lane & 15);
                int px   = pxw + h * 16 + ((lane & 16) ? 8 : 0);
                uint32_t ad = (uint32_t)__cvta_generic_to_shared(sF + krow * FROW + px);
                ldsm_x4_trans(bfr[h], ad);
            }
            #pragma unroll
            for (int nt = 0; nt < 4; nt++)
                mma_bf16(acc[nt], a,
                         bfr[nt >> 1][(nt & 1) * 2 + 0],
                         bfr[nt >> 1][(nt & 1) * 2 + 1]);
        }
        #pragma unroll
        for (int nt = 0; nt < 4; nt++) {
            rm0[nt] = fmaxf(rm0[nt], fmaxf(acc[nt][0], acc[nt][2]));
            rm1[nt] = fmaxf(rm1[nt], fmaxf(acc[nt][1], acc[nt][3]));
        }
    }

    // cross-lane max (rows live on lanes sharing lane&3)
    float* pmax = &d_pooled[z][b][1][tile * PXT];
    #pragma unroll
    for (int nt = 0; nt < 4; nt++) {
        float m0 = rm0[nt], m1 = rm1[nt];
        #pragma unroll
        for (int off = 4; off < 32; off <<= 1) {
            m0 = fmaxf(m0, __shfl_xor_sync(0xffffffffu, m0, off));
            m1 = fmaxf(m1, __shfl_xor_sync(0xffffffffu, m1, off));
        }
        if (lane < 4) {
            int px = pxw + nt * 8 + lane * 2;
            pmax[px]     = m0;
            pmax[px + 1] = m1;
        }
    }

    // mean: w . f
    float s = 0.f;
    const __nv_bfloat16* colp = sF + pxw + lane;
    #pragma unroll 16
    for (int k = 0; k < 64; k++)
        s += sw[k] * __bfloat162float(colp[k * FROW]);
    d_pooled[z][b][0][tile * PXT + pxw + lane] = s;
}

// ---------------- kernel 5: fused conv1+conv2 + softmax partials ------------
#define CTX 64
#define CTY 16
__global__ void __launch_bounds__(256)
convf_kernel(const float* __restrict__ cw1, const float* __restrict__ cb1,
             const float* __restrict__ cw2, const float* __restrict__ cb2) {
    __shared__ float in0[20][68];
    __shared__ float in1[20][68];
    __shared__ float t1s[18][66];
    __shared__ float rbuf[256];

    int tid = threadIdx.x;
    int ox = blockIdx.x * CTX;
    int oy = blockIdx.y * CTY;
    int zb = blockIdx.z; int z = zb >> 2, b = zb & 3;
    const float* p0 = d_pooled[z][b][0];
    const float* p1 = d_pooled[z][b][1];

    float w1r[18], w2r[9];
    #pragma unroll
    for (int i = 0; i < 18; i++) w1r[i] = cw1[i];
    #pragma unroll
    for (int i = 0; i < 9;  i++) w2r[i] = cw2[i];
    float bias1 = cb1[0], bias2 = cb2[0];

    for (int idx = tid; idx < 20 * 68; idx += 256) {
        int ly = idx / 68, lx = idx % 68;
        int gy = oy - 2 + ly, gx = ox - 2 + lx;
        bool ok = (gy >= 0) & (gy < 256) & (gx >= 0) & (gx < 256);
        int q = gy * 256 + gx;
        in0[ly][lx] = ok ? p0[q] : 0.f;
        in1[ly][lx] = ok ? p1[q] : 0.f;
    }
    __syncthreads();

    for (int idx = tid; idx < 18 * 66; idx += 256) {
        int ty = idx / 66, tx = idx % 66;
        int gy = oy - 1 + ty, gx = ox - 1 + tx;
        float v = 0.f;
        if ((gy >= 0) & (gy < 256) & (gx >= 0) & (gx < 256)) {
            float acc = bias1;
            #pragma unroll
            for (int dy = 0; dy < 3; dy++)
                #pragma unroll
                for (int dx = 0; dx < 3; dx++) {
                    acc += w1r[dy * 3 + dx]     * in0[ty + dy][tx + dx];
                    acc += w1r[9 + dy * 3 + dx] * in1[ty + dy][tx + dx];
                }
            v = fmaxf(acc, 0.f);
        }
        t1s[ty][tx] = v;
    }
    __syncthreads();

    float vals[4];
    #pragma unroll
    for (int r = 0; r < 4; r++) {
        int idx = tid + r * 256;
        int y = idx >> 6, x = idx & 63;
        float acc = bias2;
        #pragma unroll
        for (int dy = 0; dy < 3; dy++)
            #pragma unroll
            for (int dx = 0; dx < 3; dx++)
                acc += w2r[dy * 3 + dx] * t1s[y + dy][x + dx];
        vals[r] = acc;
        d_t2[z][b][(oy + y) * 256 + (ox + x)] = acc;
    }

    float lm = fmaxf(fmaxf(vals[0], vals[1]), fmaxf(vals[2], vals[3]));
    rbuf[tid] = lm;
    __syncthreads();
    for (int o = 128; o > 0; o >>= 1) {
        if (tid < o) rbuf[tid] = fmaxf(rbuf[tid], rbuf[tid + o]);
        __syncthreads();
    }
    float Mblk = rbuf[0];
    __syncthreads();
    float ls = __expf(vals[0] - Mblk) + __expf(vals[1] - Mblk)
             + __expf(vals[2] - Mblk) + __expf(vals[3] - Mblk);
    rbuf[tid] = ls;
    __syncthreads();
    for (int o = 128; o > 0; o >>= 1) {
        if (tid < o) rbuf[tid] += rbuf[tid + o];
        __syncthreads();
    }
    if (tid == 0) {
        int blk = blockIdx.y * 4 + blockIdx.x;
        d_cmax[zb][blk] = Mblk;
        d_csum[zb][blk] = rbuf[0];
    }
}

// ---------------- kernel 6: gate = softmax(t2) over HW ----------------------
__global__ void gate_kernel() {
    __shared__ float sM, sS;
    int tid = threadIdx.x;
    int zb = blockIdx.y; int z = zb >> 2, b = zb & 3;

    if (tid < 32) {
        float m0 = d_cmax[zb][tid], m1 = d_cmax[zb][tid + 32];
        float mm = fmaxf(m0, m1);
        #pragma unroll
        for (int off = 16; off > 0; off >>= 1)
            mm = fmaxf(mm, __shfl_xor_sync(0xffffffffu, mm, off));
        float s = d_csum[zb][tid]      * __expf(m0 - mm)
                + d_csum[zb][tid + 32] * __expf(m1 - mm);
        #pragma unroll
        for (int off = 16; off > 0; off >>= 1)
            s += __shfl_xor_sync(0xffffffffu, s, off);
        if (tid == 0) { sM = mm; sS = s; }
    }
    __syncthreads();
    float M = sM, rinv = 1.f / sS;

    int i4 = blockIdx.x * 256 + tid;
    float4 yv = *(const float4*)(&d_t2[z][b][i4 * 4]);
    float4 g;
    g.x = __expf(yv.x - M) * rinv;
    g.y = __expf(yv.y - M) * rinv;
    g.z = __expf(yv.z - M) * rinv;
    g.w = __expf(yv.w - M) * rinv;
    *(float4*)(&d_g[z][b][i4 * 4]) = g;
}

// ---------------- kernel 7: o = f*(1+g), 2 float4 per thread ----------------
__global__ void out_kernel(const float* __restrict__ f1,
                           const float* __restrict__ f2,
                           float* __restrict__ out) {
    unsigned idx  = blockIdx.x * 256u + threadIdx.x;
    unsigned pr   = idx & 8191u;
    unsigned c    = (idx >> 13) & 63u;
    unsigned b    = (idx >> 19) & 3u;
    unsigned z    = 1u - (idx >> 21);
    const float* f = z ? f2 : f1;

    const float4* gp = (const float4*)&d_g[z][b][pr * 8];
    float4 g0 = gp[0], g1 = gp[1];
    size_t base = ((size_t)(b * 64u + c)) * HW + pr * 8u;
    const float4* fp = (const float4*)(f + base);
    float4 v0 = fp[0], v1 = fp[1];
    float4 o0, o1;
    o0.x = fmaf(v0.x, g0.x, v0.x); o0.y = fmaf(v0.y, g0.y, v0.y);
    o0.z = fmaf(v0.z, g0.z, v0.z); o0.w = fmaf(v0.w, g0.w, v0.w);
    o1.x = fmaf(v1.x, g1.x, v1.x); o1.y = fmaf(v1.y, g1.y, v1.y);
    o1.z = fmaf(v1.z, g1.z, v1.z); o1.w = fmaf(v1.w, g1.w, v1.w);
    float4* op = (float4*)(out + (size_t)z * ((size_t)B * C * HW) + base);
    op[0] = o0; op[1] = o1;
}

// ---------------- launch ------------------------------------------------------
extern "C" void kernel_launch(void* const* d_in, const int* in_sizes, int n_in,
                              void* d_out, int out_size) {
    const float* f1 = (const float*)d_in[0];
    const float* f2 = (const float*)d_in[1];

    cudaFuncSetAttribute(atpool_kernel,
                         cudaFuncAttributeMaxDynamicSharedMemorySize,
                         ATP_SMEM_BYTES);

    stats_kernel<<<2048, 256>>>(f1, f2);

    mlp_kernel<<<1, 256>>>(
        (const float*)d_in[2],  (const float*)d_in[3],
        (const float*)d_in[4],  (const float*)d_in[5],
        (const float*)d_in[6],  (const float*)d_in[7],
        (const float*)d_in[8],  (const float*)d_in[9],
        (const float*)d_in[10], (const float*)d_in[11],
        (const float*)d_in[12], (const float*)d_in[13],
        (const float*)d_in[14], (const float*)d_in[15],
        (const float*)d_in[16], (const float*)d_in[17]);

    sprep_kernel<<<8, 256>>>();

    atpool_kernel<<<dim3(256, 4, 2), 256, ATP_SMEM_BYTES>>>(f1, f2);

    convf_kernel<<<dim3(4, 16, 8), 256>>>(
        (const float*)d_in[18], (const float*)d_in[19],
        (const float*)d_in[20], (const float*)d_in[21]);

    gate_kernel<<<dim3(64, 8), 256>>>();

    out_kernel<<<16384, 256>>>(f1, f2, (float*)d_out);
}